// round 1
// baseline (speedup 1.0000x reference)
#include <cuda_runtime.h>
#include <cuda_bf16.h>
#include <math.h>

// Problem dims (fixed by reference)
#define BB 8
#define SLQ 2048
#define SLK 2048
#define DQ 1024   // QD (model dim after projection)
#define DK 512    // KD (key input dim)
#define DV 512    // VD (value input dim)

// Scratch (device globals: allocation-free rule)
__device__ float g_q[(size_t)BB * SLQ * DQ];          // 64 MB
__device__ float g_k[(size_t)BB * SLK * DQ];          // 64 MB
__device__ float g_v[(size_t)BB * SLK * DQ];          // 64 MB
__device__ float g_s[(size_t)BB * SLQ * SLK];         // 128 MB (scores -> probs)

// ----------------------------------------------------------------------------
// 128x128x8 SGEMM, 256 threads, 8x8 per-thread register tile.
// TRANSB=0: C[M,N] = A[M,K] * B[K,N] (+bias)       (row-major A, B)
// TRANSB=1: C[M,N] = A[M,K] * B[N,K]^T              (row-major A, B)
// All of M%128==0, N%128==0, K%8==0 hold for every call here; no bounds checks.
// ----------------------------------------------------------------------------
template <int TRANSB>
__global__ __launch_bounds__(256) void gemm128(
    const float* __restrict__ A, const float* __restrict__ Bm,
    const float* __restrict__ bias, float* __restrict__ C,
    int M, int N, int K,
    size_t sA, size_t sB, size_t sC)
{
    __shared__ float As[8][128];
    __shared__ float Bs[8][128];

    const int tid = threadIdx.x;
    const int bz  = blockIdx.z;
    A  += (size_t)bz * sA;
    Bm += (size_t)bz * sB;
    C  += (size_t)bz * sC;

    const int bm = blockIdx.y * 128;
    const int bn = blockIdx.x * 128;

    // A tile loader: 128 rows x 8 cols; one float4 per thread
    const int arow = tid >> 1;              // 0..127
    const int acol = (tid & 1) * 4;         // 0 or 4
    const float* pA = A + (size_t)(bm + arow) * K + acol;

    // B tile loader
    int brow, bcol;
    const float* pB;
    if (TRANSB) {                            // B is [N,K]: load rows of B, transpose into Bs
        brow = tid >> 1;                     // n within tile, 0..127
        bcol = (tid & 1) * 4;                // k offset
        pB = Bm + (size_t)(bn + brow) * K + bcol;
    } else {                                 // B is [K,N]
        brow = tid >> 5;                     // k, 0..7
        bcol = (tid & 31) * 4;               // n offset
        pB = Bm + (size_t)brow * N + bn + bcol;
    }

    const int trow = (tid >> 4) * 8;         // output row offset in tile
    const int tcol = (tid & 15) * 8;         // output col offset in tile

    float acc[8][8];
#pragma unroll
    for (int i = 0; i < 8; i++)
#pragma unroll
        for (int j = 0; j < 8; j++) acc[i][j] = 0.0f;

    float4 a4 = *(const float4*)pA;
    float4 b4 = *(const float4*)pB;

    for (int k0 = 0; k0 < K; k0 += 8) {
        // stage current tiles into smem (A and TRANSB-B scattered/transposed)
        As[acol + 0][arow] = a4.x;
        As[acol + 1][arow] = a4.y;
        As[acol + 2][arow] = a4.z;
        As[acol + 3][arow] = a4.w;
        if (TRANSB) {
            Bs[bcol + 0][brow] = b4.x;
            Bs[bcol + 1][brow] = b4.y;
            Bs[bcol + 2][brow] = b4.z;
            Bs[bcol + 3][brow] = b4.w;
        } else {
            *(float4*)&Bs[brow][bcol] = b4;
        }
        __syncthreads();

        // prefetch next tiles into registers while computing
        float4 an = a4, bn4 = b4;
        if (k0 + 8 < K) {
            pA += 8;
            if (TRANSB) pB += 8; else pB += (size_t)8 * N;
            an  = *(const float4*)pA;
            bn4 = *(const float4*)pB;
        }

#pragma unroll
        for (int kk = 0; kk < 8; kk++) {
            float a[8], b[8];
            *(float4*)&a[0] = *(const float4*)&As[kk][trow];
            *(float4*)&a[4] = *(const float4*)&As[kk][trow + 4];
            *(float4*)&b[0] = *(const float4*)&Bs[kk][tcol];
            *(float4*)&b[4] = *(const float4*)&Bs[kk][tcol + 4];
#pragma unroll
            for (int i = 0; i < 8; i++)
#pragma unroll
                for (int j = 0; j < 8; j++)
                    acc[i][j] = fmaf(a[i], b[j], acc[i][j]);
        }
        __syncthreads();
        a4 = an; b4 = bn4;
    }

    // epilogue (+ optional bias), float4 stores
    float bv[8];
#pragma unroll
    for (int j = 0; j < 8; j++) bv[j] = bias ? bias[bn + tcol + j] : 0.0f;

#pragma unroll
    for (int i = 0; i < 8; i++) {
        float* cp = C + (size_t)(bm + trow + i) * N + bn + tcol;
        float4 o0, o1;
        o0.x = acc[i][0] + bv[0]; o0.y = acc[i][1] + bv[1];
        o0.z = acc[i][2] + bv[2]; o0.w = acc[i][3] + bv[3];
        o1.x = acc[i][4] + bv[4]; o1.y = acc[i][5] + bv[5];
        o1.z = acc[i][6] + bv[6]; o1.w = acc[i][7] + bv[7];
        *(float4*)cp       = o0;
        *(float4*)(cp + 4) = o1;
    }
}

// ----------------------------------------------------------------------------
// Row softmax over `cols` (=2048) elements, one block (256 thr) per row, in place.
// fp32 throughout, max-subtraction (logits reach ~±46 here).
// ----------------------------------------------------------------------------
__global__ __launch_bounds__(256) void softmax_rows(float* __restrict__ S, int cols)
{
    __shared__ float red[8];
    const size_t row = blockIdx.x;
    float* p = S + row * (size_t)cols;
    const int tid = threadIdx.x;

    // ---- max ----
    float m = -1e30f;
    for (int j = tid; j < cols; j += 256) m = fmaxf(m, p[j]);
#pragma unroll
    for (int o = 16; o > 0; o >>= 1) m = fmaxf(m, __shfl_xor_sync(0xFFFFFFFFu, m, o));
    if ((tid & 31) == 0) red[tid >> 5] = m;
    __syncthreads();
    if (tid < 32) {
        float v = (tid < 8) ? red[tid] : -1e30f;
#pragma unroll
        for (int o = 4; o > 0; o >>= 1) v = fmaxf(v, __shfl_xor_sync(0xFFFFFFFFu, v, o));
        if (tid == 0) red[0] = v;
    }
    __syncthreads();
    m = red[0];
    __syncthreads();

    // ---- exp + sum ----
    float s = 0.0f;
    for (int j = tid; j < cols; j += 256) {
        float e = expf(p[j] - m);
        p[j] = e;
        s += e;
    }
#pragma unroll
    for (int o = 16; o > 0; o >>= 1) s += __shfl_xor_sync(0xFFFFFFFFu, s, o);
    if ((tid & 31) == 0) red[tid >> 5] = s;
    __syncthreads();
    if (tid < 32) {
        float v = (tid < 8) ? red[tid] : 0.0f;
#pragma unroll
        for (int o = 4; o > 0; o >>= 1) v += __shfl_xor_sync(0xFFFFFFFFu, v, o);
        if (tid == 0) red[0] = v;
    }
    __syncthreads();
    const float inv = 1.0f / red[0];

    // ---- normalize ----
    for (int j = tid; j < cols; j += 256) p[j] *= inv;
}

// ----------------------------------------------------------------------------
// Launch: 3 projections -> batched QK^T -> softmax -> batched PV
// ----------------------------------------------------------------------------
extern "C" void kernel_launch(void* const* d_in, const int* in_sizes, int n_in,
                              void* d_out, int out_size)
{
    const float* query = (const float*)d_in[0];   // [B, LQ, 1024]
    const float* key   = (const float*)d_in[1];   // [B, LK, 512]
    const float* value = (const float*)d_in[2];   // [B, LK, 512]
    const float* Wq    = (const float*)d_in[3];   // [1024, 1024]
    const float* bq    = (const float*)d_in[4];
    const float* Wk    = (const float*)d_in[5];   // [512, 1024]
    const float* bk    = (const float*)d_in[6];
    const float* Wv    = (const float*)d_in[7];   // [512, 1024]
    const float* bv    = (const float*)d_in[8];
    float* out = (float*)d_out;                   // [B, LQ, 1024]

    float *q, *k, *v, *s;
    cudaGetSymbolAddress((void**)&q, g_q);
    cudaGetSymbolAddress((void**)&k, g_k);
    cudaGetSymbolAddress((void**)&v, g_v);
    cudaGetSymbolAddress((void**)&s, g_s);

    const int Mflat = BB * SLQ;   // 16384 rows, projections shared across batch

    // Q = query @ Wq + bq : [16384,1024] x [1024,1024]
    {
        dim3 grid(DQ / 128, Mflat / 128, 1);
        gemm128<0><<<grid, 256>>>(query, Wq, bq, q, Mflat, DQ, DQ, 0, 0, 0);
    }
    // K = key @ Wk + bk : [16384,512] x [512,1024]
    {
        dim3 grid(DQ / 128, Mflat / 128, 1);
        gemm128<0><<<grid, 256>>>(key, Wk, bk, k, Mflat, DQ, DK, 0, 0, 0);
    }
    // V = value @ Wv + bv : [16384,512] x [512,1024]
    {
        dim3 grid(DQ / 128, Mflat / 128, 1);
        gemm128<0><<<grid, 256>>>(value, Wv, bv, v, Mflat, DQ, DV, 0, 0, 0);
    }
    // S = Q @ K^T per batch : [2048,1024] x [2048,1024]^T -> [2048,2048]
    {
        dim3 grid(SLK / 128, SLQ / 128, BB);
        gemm128<1><<<grid, 256>>>(q, k, nullptr, s,
                                  SLQ, SLK, DQ,
                                  (size_t)SLQ * DQ, (size_t)SLK * DQ,
                                  (size_t)SLQ * SLK);
    }
    // softmax rows of S (in place)
    softmax_rows<<<BB * SLQ, 256>>>(s, SLK);

    // out = S @ V per batch : [2048,2048] x [2048,1024]
    {
        dim3 grid(DQ / 128, SLQ / 128, BB);
        gemm128<0><<<grid, 256>>>(s, v, nullptr, out,
                                  SLQ, DQ, SLK,
                                  (size_t)SLQ * SLK, (size_t)SLK * DQ,
                                  (size_t)SLQ * DQ);
    }
}

// round 3
// speedup vs baseline: 2.6899x; 2.6899x over previous
#include <cuda_runtime.h>
#include <cuda_bf16.h>
#include <cstdint>
#include <math.h>

// ---------------- problem dims ----------------
#define BB 8
#define SLQ 2048
#define SLK 2048
#define DQ 1024
#define DK 512
#define DV 512
#define MFLAT (BB * SLQ)          // 16384

typedef __nv_bfloat16 bf16;

// ---------------- scratch (device globals; allocation-free rule) ------------
__device__ __align__(256) bf16 g_qx_hi[(size_t)MFLAT * DQ];
__device__ __align__(256) bf16 g_qx_lo[(size_t)MFLAT * DQ];
__device__ __align__(256) bf16 g_kx_hi[(size_t)MFLAT * DK];
__device__ __align__(256) bf16 g_kx_lo[(size_t)MFLAT * DK];
__device__ __align__(256) bf16 g_vx_hi[(size_t)MFLAT * DV];
__device__ __align__(256) bf16 g_vx_lo[(size_t)MFLAT * DV];
__device__ __align__(256) bf16 g_wqt_hi[(size_t)DQ * DQ];
__device__ __align__(256) bf16 g_wqt_lo[(size_t)DQ * DQ];
__device__ __align__(256) bf16 g_wkt_hi[(size_t)DQ * DK];
__device__ __align__(256) bf16 g_wkt_lo[(size_t)DQ * DK];
__device__ __align__(256) bf16 g_wvt_hi[(size_t)DQ * DV];
__device__ __align__(256) bf16 g_wvt_lo[(size_t)DQ * DV];
__device__ __align__(256) bf16 g_q_hi[(size_t)MFLAT * DQ];
__device__ __align__(256) bf16 g_q_lo[(size_t)MFLAT * DQ];
__device__ __align__(256) bf16 g_k_hi[(size_t)MFLAT * DQ];
__device__ __align__(256) bf16 g_k_lo[(size_t)MFLAT * DQ];
__device__ __align__(256) float g_v[(size_t)MFLAT * DQ];
__device__ __align__(256) bf16 g_vt_hi[(size_t)BB * DQ * SLK];
__device__ __align__(256) bf16 g_vt_lo[(size_t)BB * DQ * SLK];
__device__ __align__(256) float g_s[(size_t)BB * SLQ * SLK];
__device__ __align__(256) bf16 g_p_hi[(size_t)BB * SLQ * SLK];
__device__ __align__(256) bf16 g_p_lo[(size_t)BB * SLQ * SLK];

// ---------------- small helpers ----------------
__device__ __forceinline__ uint32_t smem_u32(const void* p) {
    uint32_t a;
    asm("{ .reg .u64 t; cvta.to.shared.u64 t, %1; cvt.u32.u64 %0, t; }" : "=r"(a) : "l"(p));
    return a;
}
// pack two floats to bf16x2: result low 16 = lo_f, high 16 = hi_f
__device__ __forceinline__ uint32_t packbf(float hi_f, float lo_f) {
    uint32_t r;
    asm("cvt.rn.bf16x2.f32 %0, %1, %2;" : "=r"(r) : "f"(hi_f), "f"(lo_f));
    return r;
}
__device__ __forceinline__ float lo_as_f(uint32_t p) { return __uint_as_float(p << 16); }
__device__ __forceinline__ float hi_as_f(uint32_t p) { return __uint_as_float(p & 0xffff0000u); }

__device__ __forceinline__ void cp16(uint32_t dst, const void* src) {
    asm volatile("cp.async.cg.shared.global [%0], [%1], 16;" :: "r"(dst), "l"(src));
}
__device__ __forceinline__ void ldm4(uint32_t (&r)[4], uint32_t a) {
    asm volatile("ldmatrix.sync.aligned.m8n8.x4.shared.b16 {%0,%1,%2,%3}, [%4];"
                 : "=r"(r[0]), "=r"(r[1]), "=r"(r[2]), "=r"(r[3]) : "r"(a));
}
__device__ __forceinline__ void mma16816(float* d, const uint32_t* a, uint32_t b0, uint32_t b1) {
    asm volatile("mma.sync.aligned.m16n8k16.row.col.f32.bf16.bf16.f32 "
                 "{%0,%1,%2,%3}, {%4,%5,%6,%7}, {%8,%9}, {%0,%1,%2,%3};"
                 : "+f"(d[0]), "+f"(d[1]), "+f"(d[2]), "+f"(d[3])
                 : "r"(a[0]), "r"(a[1]), "r"(a[2]), "r"(a[3]), "r"(b0), "r"(b1));
}

// ---------------- GEMM: C[M,N] = A[M,K] * B[N,K]^T, bf16 split, fp32 acc -----
// MODE 0: fp32 out (+optional bias). MODE 1: split bf16 hi/lo out (+bias).
#define ROWB   80                  // smem bytes per 32-bf16 row (conflict-free)
#define TILEB  (128 * ROWB)        // 10240
#define STAGEB (4 * TILEB)         // 40960 : Ahi, Alo, Bhi, Blo
#define GSMEM  (2 * STAGEB)        // 81920

template <int MODE>
__global__ __launch_bounds__(256, 2) void gemm_mma(
    const bf16* __restrict__ Ahi, const bf16* __restrict__ Alo,
    const bf16* __restrict__ Bhi, const bf16* __restrict__ Blo,
    const float* __restrict__ bias,
    float* __restrict__ Cf, bf16* __restrict__ Chi, bf16* __restrict__ Clo,
    int M, int N, int K, size_t sA, size_t sB, size_t sC)
{
    extern __shared__ char smem[];
    const uint32_t sb = smem_u32(smem);
    const int tid = threadIdx.x, wid = tid >> 5, lane = tid & 31;
    const int bz = blockIdx.z;
    const int bm = blockIdx.y * 128, bn = blockIdx.x * 128;

    Ahi += (size_t)bz * sA; Alo += (size_t)bz * sA;
    Bhi += (size_t)bz * sB; Blo += (size_t)bz * sB;

    const bf16* src[4] = { Ahi + (size_t)bm * K, Alo + (size_t)bm * K,
                           Bhi + (size_t)bn * K, Blo + (size_t)bn * K };

    const int wm = wid & 3, wn = wid >> 2;       // warp tile 32(M) x 64(N)
    // ldmatrix per-lane offsets (bytes) within a tile buffer
    const uint32_t a_l = (uint32_t)((wm * 32 + (lane & 7) + ((lane >> 3) & 1) * 8) * ROWB
                                    + ((lane >> 4) & 1) * 16);
    const uint32_t b_l = (uint32_t)((wn * 64 + (lane & 7) + ((lane >> 4) & 1) * 8) * ROWB
                                    + ((lane >> 3) & 1) * 16);

    float acc[2][8][4];
#pragma unroll
    for (int m = 0; m < 2; m++)
#pragma unroll
        for (int n = 0; n < 8; n++)
#pragma unroll
            for (int j = 0; j < 4; j++) acc[m][n][j] = 0.0f;

    const int nc = K >> 5;   // chunks of 32

    auto load_stage = [&](int c, int stage) {
        const int k0 = c << 5;
#pragma unroll
        for (int t = 0; t < 8; t++) {
            const int idx = tid + t * 256;           // 0..2047
            const int tile = idx >> 9;               // 0..3
            const int r = (idx >> 2) & 127;          // row in tile
            const int ch = idx & 3;                  // 16B chunk
            const bf16* s2 = src[tile] + (size_t)r * K + k0 + ch * 8;
            cp16(sb + stage * STAGEB + tile * TILEB + r * ROWB + ch * 16, s2);
        }
        asm volatile("cp.async.commit_group;" ::: "memory");
    };

    load_stage(0, 0);

    for (int c = 0; c < nc; c++) {
        const int stage = c & 1;
        if (c + 1 < nc) {
            load_stage(c + 1, stage ^ 1);
            asm volatile("cp.async.wait_group 1;" ::: "memory");
        } else {
            asm volatile("cp.async.wait_group 0;" ::: "memory");
        }
        __syncthreads();

        const uint32_t base = sb + stage * STAGEB;
#pragma unroll
        for (int ks = 0; ks < 2; ks++) {
            const uint32_t koff = ks * 32;
            uint32_t ah[2][4], al[2][4];
            ldm4(ah[0], base + a_l + koff);
            ldm4(ah[1], base + a_l + koff + 16 * ROWB);
            ldm4(al[0], base + TILEB + a_l + koff);
            ldm4(al[1], base + TILEB + a_l + koff + 16 * ROWB);
#pragma unroll
            for (int g = 0; g < 4; g++) {
                uint32_t bh[4], bl[4];
                ldm4(bh, base + 2 * TILEB + b_l + koff + g * 16 * ROWB);
                ldm4(bl, base + 3 * TILEB + b_l + koff + g * 16 * ROWB);
#pragma unroll
                for (int m = 0; m < 2; m++) {
                    mma16816(acc[m][2 * g],     ah[m], bh[0], bh[1]);
                    mma16816(acc[m][2 * g + 1], ah[m], bh[2], bh[3]);
                    mma16816(acc[m][2 * g],     al[m], bh[0], bh[1]);
                    mma16816(acc[m][2 * g + 1], al[m], bh[2], bh[3]);
                    mma16816(acc[m][2 * g],     ah[m], bl[0], bl[1]);
                    mma16816(acc[m][2 * g + 1], ah[m], bl[2], bl[3]);
                }
            }
        }
        __syncthreads();
    }

    // ---- epilogue ----
    const int row0 = bm + wm * 32 + (lane >> 2);
    const int col0 = bn + wn * 64 + (lane & 3) * 2;
#pragma unroll
    for (int m = 0; m < 2; m++) {
#pragma unroll
        for (int nt = 0; nt < 8; nt++) {
            const int r = row0 + m * 16;
            const int cc = col0 + nt * 8;
            float b0 = 0.f, b1 = 0.f;
            if (bias) { b0 = bias[cc]; b1 = bias[cc + 1]; }
            const float x0 = acc[m][nt][0] + b0, x1 = acc[m][nt][1] + b1;
            const float y0 = acc[m][nt][2] + b0, y1 = acc[m][nt][3] + b1;
            if (MODE == 0) {
                float* p0 = Cf + (size_t)bz * sC + (size_t)r * N + cc;
                float* p1 = Cf + (size_t)bz * sC + (size_t)(r + 8) * N + cc;
                *(float2*)p0 = make_float2(x0, x1);
                *(float2*)p1 = make_float2(y0, y1);
            } else {
                const uint32_t hx = packbf(x1, x0);
                const uint32_t lx = packbf(x1 - hi_as_f(hx), x0 - lo_as_f(hx));
                const uint32_t hy = packbf(y1, y0);
                const uint32_t ly = packbf(y1 - hi_as_f(hy), y0 - lo_as_f(hy));
                *(uint32_t*)(Chi + (size_t)bz * sC + (size_t)r * N + cc) = hx;
                *(uint32_t*)(Clo + (size_t)bz * sC + (size_t)r * N + cc) = lx;
                *(uint32_t*)(Chi + (size_t)bz * sC + (size_t)(r + 8) * N + cc) = hy;
                *(uint32_t*)(Clo + (size_t)bz * sC + (size_t)(r + 8) * N + cc) = ly;
            }
        }
    }
}

// ---------------- fp32 -> bf16 hi/lo split (flat) ----------------
__global__ __launch_bounds__(256) void convert_split(
    const float4* __restrict__ in, uint2* __restrict__ hi, uint2* __restrict__ lo, size_t n4)
{
    size_t i = (size_t)blockIdx.x * blockDim.x + threadIdx.x;
    if (i >= n4) return;
    const float4 v = in[i];
    const uint32_t h01 = packbf(v.y, v.x);
    const uint32_t h23 = packbf(v.w, v.z);
    const uint32_t l01 = packbf(v.y - hi_as_f(h01), v.x - lo_as_f(h01));
    const uint32_t l23 = packbf(v.w - hi_as_f(h23), v.z - lo_as_f(h23));
    hi[i] = make_uint2(h01, h23);
    lo[i] = make_uint2(l01, l23);
}

// ---------------- fp32 [R,C] -> transposed bf16 hi/lo [C,R], batched --------
__global__ __launch_bounds__(256) void transpose_split(
    const float* __restrict__ in, bf16* __restrict__ ohi, bf16* __restrict__ olo,
    int R, int C, size_t sI, size_t sO)
{
    __shared__ float t[32][33];
    in  += (size_t)blockIdx.z * sI;
    ohi += (size_t)blockIdx.z * sO;
    olo += (size_t)blockIdx.z * sO;
    const int r0 = blockIdx.y * 32, c0 = blockIdx.x * 32;
    const int tx = threadIdx.x, ty = threadIdx.y;
#pragma unroll
    for (int j = ty; j < 32; j += 8)
        t[j][tx] = in[(size_t)(r0 + j) * C + c0 + tx];
    __syncthreads();
#pragma unroll
    for (int j = ty; j < 32; j += 8) {
        const float v = t[tx][j];
        const bf16 h = __float2bfloat16(v);
        ohi[(size_t)(c0 + j) * R + r0 + tx] = h;
        olo[(size_t)(c0 + j) * R + r0 + tx] = __float2bfloat16(v - __bfloat162float(h));
    }
}

// ---------------- softmax rows (2048) -> bf16 hi/lo probs -------------------
__global__ __launch_bounds__(256) void softmax_split(
    const float* __restrict__ S, bf16* __restrict__ Phi, bf16* __restrict__ Plo)
{
    __shared__ float red[8];
    const size_t row = blockIdx.x;
    const float* p = S + row * (size_t)SLK;
    const int tid = threadIdx.x;

    float xv[8];
#pragma unroll
    for (int j = 0; j < 8; j++) xv[j] = p[tid + j * 256];

    float m = -1e30f;
#pragma unroll
    for (int j = 0; j < 8; j++) m = fmaxf(m, xv[j]);
#pragma unroll
    for (int o = 16; o > 0; o >>= 1) m = fmaxf(m, __shfl_xor_sync(0xFFFFFFFFu, m, o));
    if ((tid & 31) == 0) red[tid >> 5] = m;
    __syncthreads();
    if (tid < 32) {
        float v = (tid < 8) ? red[tid] : -1e30f;
#pragma unroll
        for (int o = 4; o > 0; o >>= 1) v = fmaxf(v, __shfl_xor_sync(0xFFFFFFFFu, v, o));
        if (tid == 0) red[0] = v;
    }
    __syncthreads();
    m = red[0];
    __syncthreads();

    float s = 0.0f;
#pragma unroll
    for (int j = 0; j < 8; j++) { xv[j] = expf(xv[j] - m); s += xv[j]; }
#pragma unroll
    for (int o = 16; o > 0; o >>= 1) s += __shfl_xor_sync(0xFFFFFFFFu, s, o);
    if ((tid & 31) == 0) red[tid >> 5] = s;
    __syncthreads();
    if (tid < 32) {
        float v = (tid < 8) ? red[tid] : 0.0f;
#pragma unroll
        for (int o = 4; o > 0; o >>= 1) v += __shfl_xor_sync(0xFFFFFFFFu, v, o);
        if (tid == 0) red[0] = v;
    }
    __syncthreads();
    const float inv = 1.0f / red[0];

#pragma unroll
    for (int j = 0; j < 8; j++) {
        const float e = xv[j] * inv;
        const bf16 h = __float2bfloat16(e);
        Phi[row * (size_t)SLK + tid + j * 256] = h;
        Plo[row * (size_t)SLK + tid + j * 256] = __float2bfloat16(e - __bfloat162float(h));
    }
}

// ============================================================================
extern "C" void kernel_launch(void* const* d_in, const int* in_sizes, int n_in,
                              void* d_out, int out_size)
{
    const float* query = (const float*)d_in[0];
    const float* key   = (const float*)d_in[1];
    const float* value = (const float*)d_in[2];
    const float* Wq    = (const float*)d_in[3];
    const float* bq    = (const float*)d_in[4];
    const float* Wk    = (const float*)d_in[5];
    const float* bk    = (const float*)d_in[6];
    const float* Wv    = (const float*)d_in[7];
    const float* bv    = (const float*)d_in[8];
    float* out = (float*)d_out;

    bf16 *qxh, *qxl, *kxh, *kxl, *vxh, *vxl;
    bf16 *wqh, *wql, *wkh, *wkl, *wvh, *wvl;
    bf16 *qh, *ql, *kh, *kl, *vth, *vtl, *ph, *pl;
    float *v, *s;
    cudaGetSymbolAddress((void**)&qxh, g_qx_hi); cudaGetSymbolAddress((void**)&qxl, g_qx_lo);
    cudaGetSymbolAddress((void**)&kxh, g_kx_hi); cudaGetSymbolAddress((void**)&kxl, g_kx_lo);
    cudaGetSymbolAddress((void**)&vxh, g_vx_hi); cudaGetSymbolAddress((void**)&vxl, g_vx_lo);
    cudaGetSymbolAddress((void**)&wqh, g_wqt_hi); cudaGetSymbolAddress((void**)&wql, g_wqt_lo);
    cudaGetSymbolAddress((void**)&wkh, g_wkt_hi); cudaGetSymbolAddress((void**)&wkl, g_wkt_lo);
    cudaGetSymbolAddress((void**)&wvh, g_wvt_hi); cudaGetSymbolAddress((void**)&wvl, g_wvt_lo);
    cudaGetSymbolAddress((void**)&qh, g_q_hi); cudaGetSymbolAddress((void**)&ql, g_q_lo);
    cudaGetSymbolAddress((void**)&kh, g_k_hi); cudaGetSymbolAddress((void**)&kl, g_k_lo);
    cudaGetSymbolAddress((void**)&v, g_v);
    cudaGetSymbolAddress((void**)&vth, g_vt_hi); cudaGetSymbolAddress((void**)&vtl, g_vt_lo);
    cudaGetSymbolAddress((void**)&s, g_s);
    cudaGetSymbolAddress((void**)&ph, g_p_hi); cudaGetSymbolAddress((void**)&pl, g_p_lo);

    cudaFuncSetAttribute(gemm_mma<0>, cudaFuncAttributeMaxDynamicSharedMemorySize, GSMEM);
    cudaFuncSetAttribute(gemm_mma<1>, cudaFuncAttributeMaxDynamicSharedMemorySize, GSMEM);

    // -- input splits --
    convert_split<<<(unsigned)((size_t)MFLAT * DQ / 4 / 256), 256>>>(
        (const float4*)query, (uint2*)qxh, (uint2*)qxl, (size_t)MFLAT * DQ / 4);
    convert_split<<<(unsigned)((size_t)MFLAT * DK / 4 / 256), 256>>>(
        (const float4*)key, (uint2*)kxh, (uint2*)kxl, (size_t)MFLAT * DK / 4);
    convert_split<<<(unsigned)((size_t)MFLAT * DV / 4 / 256), 256>>>(
        (const float4*)value, (uint2*)vxh, (uint2*)vxl, (size_t)MFLAT * DV / 4);

    // -- weight transpose+split: W[in,out] -> Wt[out,in] --
    const dim3 tb(32, 8, 1);
    transpose_split<<<dim3(DQ / 32, DQ / 32, 1), tb>>>(Wq, wqh, wql, DQ, DQ, 0, 0);
    transpose_split<<<dim3(DQ / 32, DK / 32, 1), tb>>>(Wk, wkh, wkl, DK, DQ, 0, 0);
    transpose_split<<<dim3(DQ / 32, DV / 32, 1), tb>>>(Wv, wvh, wvl, DV, DQ, 0, 0);

    // -- projections --
    // Q: [16384,1024] = qx[16384,1024] * wqt[1024,1024]^T + bq -> split out
    gemm_mma<1><<<dim3(DQ / 128, MFLAT / 128, 1), 256, GSMEM>>>(
        qxh, qxl, wqh, wql, bq, nullptr, qh, ql, MFLAT, DQ, DQ, 0, 0, 0);
    // K: [16384,1024] = kx[16384,512] * wkt[1024,512]^T + bk -> split out
    gemm_mma<1><<<dim3(DQ / 128, MFLAT / 128, 1), 256, GSMEM>>>(
        kxh, kxl, wkh, wkl, bk, nullptr, kh, kl, MFLAT, DQ, DK, 0, 0, 0);
    // V: fp32 out
    gemm_mma<0><<<dim3(DQ / 128, MFLAT / 128, 1), 256, GSMEM>>>(
        vxh, vxl, wvh, wvl, bv, v, nullptr, nullptr, MFLAT, DQ, DV, 0, 0, 0);

    // -- V transpose+split per batch: v[B,2048,1024] -> vt[B,1024,2048] --
    transpose_split<<<dim3(DQ / 32, SLK / 32, BB), tb>>>(
        v, vth, vtl, SLK, DQ, (size_t)SLK * DQ, (size_t)SLK * DQ);

    // -- scores: S = Q K^T per batch, fp32 out --
    gemm_mma<0><<<dim3(SLK / 128, SLQ / 128, BB), 256, GSMEM>>>(
        qh, ql, kh, kl, nullptr, s, nullptr, nullptr,
        SLQ, SLK, DQ, (size_t)SLQ * DQ, (size_t)SLK * DQ, (size_t)SLQ * SLK);

    // -- softmax -> split probs --
    softmax_split<<<BB * SLQ, 256>>>(s, ph, pl);

    // -- out = P V per batch --
    gemm_mma<0><<<dim3(DQ / 128, SLQ / 128, BB), 256, GSMEM>>>(
        ph, pl, vth, vtl, nullptr, out, nullptr, nullptr,
        SLQ, DQ, SLK, (size_t)SLQ * SLK, (size_t)SLK * DQ, (size_t)SLQ * DQ);
}

// round 4
// speedup vs baseline: 4.3628x; 1.6219x over previous
#include <cuda_runtime.h>
#include <cuda_bf16.h>
#include <cstdint>
#include <math.h>

// ---------------- problem dims ----------------
#define BB 8
#define SLQ 2048
#define SLK 2048
#define DQ 1024
#define DK 512
#define DV 512
#define MFLAT (BB * SLQ)          // 16384

typedef __nv_bfloat16 bf16;

// ---------------- scratch (device globals; allocation-free rule) ------------
__device__ __align__(256) bf16 g_qx_hi[(size_t)MFLAT * DQ];
__device__ __align__(256) bf16 g_qx_lo[(size_t)MFLAT * DQ];
__device__ __align__(256) bf16 g_kx_hi[(size_t)MFLAT * DK];
__device__ __align__(256) bf16 g_kx_lo[(size_t)MFLAT * DK];
__device__ __align__(256) bf16 g_wq_hi[(size_t)DQ * DQ];     // Wq as-is [1024,1024]
__device__ __align__(256) bf16 g_wq_lo[(size_t)DQ * DQ];
__device__ __align__(256) bf16 g_wk_hi[(size_t)DK * DQ];     // Wk as-is [512,1024]
__device__ __align__(256) bf16 g_wk_lo[(size_t)DK * DQ];
__device__ __align__(256) bf16 g_wvt_hi[(size_t)DQ * DV];    // Wv^T [1024,512]
__device__ __align__(256) bf16 g_wvt_lo[(size_t)DQ * DV];
__device__ __align__(256) bf16 g_vt_hi[(size_t)BB * DV * SLK];  // value^T [B,512,2048]
__device__ __align__(256) bf16 g_vt_lo[(size_t)BB * DV * SLK];
__device__ __align__(256) bf16 g_mt_hi[(size_t)DK * DQ];     // Mt = Wk Wq^T [512,1024]
__device__ __align__(256) bf16 g_mt_lo[(size_t)DK * DQ];
__device__ __align__(256) bf16 g_t_hi[(size_t)MFLAT * DK];   // T = q Mt^T [16384,512]
__device__ __align__(256) bf16 g_t_lo[(size_t)MFLAT * DK];
__device__ __align__(256) bf16 g_u_hi[(size_t)MFLAT * DV];   // U = P v [16384,512]
__device__ __align__(256) bf16 g_u_lo[(size_t)MFLAT * DV];
__device__ __align__(256) float g_s[(size_t)BB * SLQ * SLK];    // scores fp32
__device__ __align__(256) bf16 g_p_hi[(size_t)BB * SLQ * SLK];  // probs split
__device__ __align__(256) bf16 g_p_lo[(size_t)BB * SLQ * SLK];
__device__ __align__(256) float g_wbq[DK];                      // Wk . bq  [512]
__device__ __align__(256) float g_vvec[MFLAT];                  // key . (Wk bq)  [B*2048]

// ---------------- small helpers ----------------
__device__ __forceinline__ uint32_t smem_u32(const void* p) {
    uint32_t a;
    asm("{ .reg .u64 t; cvta.to.shared.u64 t, %1; cvt.u32.u64 %0, t; }" : "=r"(a) : "l"(p));
    return a;
}
__device__ __forceinline__ uint32_t packbf(float hi_f, float lo_f) {
    uint32_t r;
    asm("cvt.rn.bf16x2.f32 %0, %1, %2;" : "=r"(r) : "f"(hi_f), "f"(lo_f));
    return r;
}
__device__ __forceinline__ float lo_as_f(uint32_t p) { return __uint_as_float(p << 16); }
__device__ __forceinline__ float hi_as_f(uint32_t p) { return __uint_as_float(p & 0xffff0000u); }

__device__ __forceinline__ void cp16(uint32_t dst, const void* src) {
    asm volatile("cp.async.cg.shared.global [%0], [%1], 16;" :: "r"(dst), "l"(src));
}
__device__ __forceinline__ void ldm4(uint32_t (&r)[4], uint32_t a) {
    asm volatile("ldmatrix.sync.aligned.m8n8.x4.shared.b16 {%0,%1,%2,%3}, [%4];"
                 : "=r"(r[0]), "=r"(r[1]), "=r"(r[2]), "=r"(r[3]) : "r"(a));
}
__device__ __forceinline__ void mma16816(float* d, const uint32_t* a, uint32_t b0, uint32_t b1) {
    asm volatile("mma.sync.aligned.m16n8k16.row.col.f32.bf16.bf16.f32 "
                 "{%0,%1,%2,%3}, {%4,%5,%6,%7}, {%8,%9}, {%0,%1,%2,%3};"
                 : "+f"(d[0]), "+f"(d[1]), "+f"(d[2]), "+f"(d[3])
                 : "r"(a[0]), "r"(a[1]), "r"(a[2]), "r"(a[3]), "r"(b0), "r"(b1));
}

// ---------------- GEMM: C[M,N] = A[M,K] * B[N,K]^T, bf16 split, fp32 acc -----
#define ROWB   80
#define TILEB  (128 * ROWB)
#define STAGEB (4 * TILEB)
#define GSMEM  (2 * STAGEB)

template <int MODE>   // 0: fp32 out (+bias). 1: split bf16 hi/lo out (+bias).
__global__ __launch_bounds__(256, 2) void gemm_mma(
    const bf16* __restrict__ Ahi, const bf16* __restrict__ Alo,
    const bf16* __restrict__ Bhi, const bf16* __restrict__ Blo,
    const float* __restrict__ bias,
    float* __restrict__ Cf, bf16* __restrict__ Chi, bf16* __restrict__ Clo,
    int M, int N, int K, size_t sA, size_t sB, size_t sC)
{
    extern __shared__ char smem[];
    const uint32_t sb = smem_u32(smem);
    const int tid = threadIdx.x, wid = tid >> 5, lane = tid & 31;
    const int bz = blockIdx.z;
    const int bm = blockIdx.y * 128, bn = blockIdx.x * 128;

    Ahi += (size_t)bz * sA; Alo += (size_t)bz * sA;
    Bhi += (size_t)bz * sB; Blo += (size_t)bz * sB;

    const bf16* src[4] = { Ahi + (size_t)bm * K, Alo + (size_t)bm * K,
                           Bhi + (size_t)bn * K, Blo + (size_t)bn * K };

    const int wm = wid & 3, wn = wid >> 2;
    const uint32_t a_l = (uint32_t)((wm * 32 + (lane & 7) + ((lane >> 3) & 1) * 8) * ROWB
                                    + ((lane >> 4) & 1) * 16);
    const uint32_t b_l = (uint32_t)((wn * 64 + (lane & 7) + ((lane >> 4) & 1) * 8) * ROWB
                                    + ((lane >> 3) & 1) * 16);

    float acc[2][8][4];
#pragma unroll
    for (int m = 0; m < 2; m++)
#pragma unroll
        for (int n = 0; n < 8; n++)
#pragma unroll
            for (int j = 0; j < 4; j++) acc[m][n][j] = 0.0f;

    const int nc = K >> 5;

    auto load_stage = [&](int c, int stage) {
        const int k0 = c << 5;
#pragma unroll
        for (int t = 0; t < 8; t++) {
            const int idx = tid + t * 256;
            const int tile = idx >> 9;
            const int r = (idx >> 2) & 127;
            const int ch = idx & 3;
            const bf16* s2 = src[tile] + (size_t)r * K + k0 + ch * 8;
            cp16(sb + stage * STAGEB + tile * TILEB + r * ROWB + ch * 16, s2);
        }
        asm volatile("cp.async.commit_group;" ::: "memory");
    };

    load_stage(0, 0);

    for (int c = 0; c < nc; c++) {
        const int stage = c & 1;
        if (c + 1 < nc) {
            load_stage(c + 1, stage ^ 1);
            asm volatile("cp.async.wait_group 1;" ::: "memory");
        } else {
            asm volatile("cp.async.wait_group 0;" ::: "memory");
        }
        __syncthreads();

        const uint32_t base = sb + stage * STAGEB;
#pragma unroll
        for (int ks = 0; ks < 2; ks++) {
            const uint32_t koff = ks * 32;
            uint32_t ah[2][4], al[2][4];
            ldm4(ah[0], base + a_l + koff);
            ldm4(ah[1], base + a_l + koff + 16 * ROWB);
            ldm4(al[0], base + TILEB + a_l + koff);
            ldm4(al[1], base + TILEB + a_l + koff + 16 * ROWB);
#pragma unroll
            for (int g = 0; g < 4; g++) {
                uint32_t bh[4], bl[4];
                ldm4(bh, base + 2 * TILEB + b_l + koff + g * 16 * ROWB);
                ldm4(bl, base + 3 * TILEB + b_l + koff + g * 16 * ROWB);
#pragma unroll
                for (int m = 0; m < 2; m++) {
                    mma16816(acc[m][2 * g],     ah[m], bh[0], bh[1]);
                    mma16816(acc[m][2 * g + 1], ah[m], bh[2], bh[3]);
                    mma16816(acc[m][2 * g],     al[m], bh[0], bh[1]);
                    mma16816(acc[m][2 * g + 1], al[m], bh[2], bh[3]);
                    mma16816(acc[m][2 * g],     ah[m], bl[0], bl[1]);
                    mma16816(acc[m][2 * g + 1], ah[m], bl[2], bl[3]);
                }
            }
        }
        __syncthreads();
    }

    const int row0 = bm + wm * 32 + (lane >> 2);
    const int col0 = bn + wn * 64 + (lane & 3) * 2;
#pragma unroll
    for (int m = 0; m < 2; m++) {
#pragma unroll
        for (int nt = 0; nt < 8; nt++) {
            const int r = row0 + m * 16;
            const int cc = col0 + nt * 8;
            float b0 = 0.f, b1 = 0.f;
            if (bias) { b0 = bias[cc]; b1 = bias[cc + 1]; }
            const float x0 = acc[m][nt][0] + b0, x1 = acc[m][nt][1] + b1;
            const float y0 = acc[m][nt][2] + b0, y1 = acc[m][nt][3] + b1;
            if (MODE == 0) {
                float* p0 = Cf + (size_t)bz * sC + (size_t)r * N + cc;
                float* p1 = Cf + (size_t)bz * sC + (size_t)(r + 8) * N + cc;
                *(float2*)p0 = make_float2(x0, x1);
                *(float2*)p1 = make_float2(y0, y1);
            } else {
                const uint32_t hx = packbf(x1, x0);
                const uint32_t lx = packbf(x1 - hi_as_f(hx), x0 - lo_as_f(hx));
                const uint32_t hy = packbf(y1, y0);
                const uint32_t ly = packbf(y1 - hi_as_f(hy), y0 - lo_as_f(hy));
                *(uint32_t*)(Chi + (size_t)bz * sC + (size_t)r * N + cc) = hx;
                *(uint32_t*)(Clo + (size_t)bz * sC + (size_t)r * N + cc) = lx;
                *(uint32_t*)(Chi + (size_t)bz * sC + (size_t)(r + 8) * N + cc) = hy;
                *(uint32_t*)(Clo + (size_t)bz * sC + (size_t)(r + 8) * N + cc) = ly;
            }
        }
    }
}

// ---------------- fp32 -> bf16 hi/lo split (flat) ----------------
__global__ __launch_bounds__(256) void convert_split(
    const float4* __restrict__ in, uint2* __restrict__ hi, uint2* __restrict__ lo, size_t n4)
{
    size_t i = (size_t)blockIdx.x * blockDim.x + threadIdx.x;
    if (i >= n4) return;
    const float4 v = in[i];
    const uint32_t h01 = packbf(v.y, v.x);
    const uint32_t h23 = packbf(v.w, v.z);
    const uint32_t l01 = packbf(v.y - hi_as_f(h01), v.x - lo_as_f(h01));
    const uint32_t l23 = packbf(v.w - hi_as_f(h23), v.z - lo_as_f(h23));
    hi[i] = make_uint2(h01, h23);
    lo[i] = make_uint2(l01, l23);
}

// ---------------- fp32 [R,C] -> transposed bf16 hi/lo [C,R], batched --------
__global__ __launch_bounds__(256) void transpose_split(
    const float* __restrict__ in, bf16* __restrict__ ohi, bf16* __restrict__ olo,
    int R, int C, size_t sI, size_t sO)
{
    __shared__ float t[32][33];
    in  += (size_t)blockIdx.z * sI;
    ohi += (size_t)blockIdx.z * sO;
    olo += (size_t)blockIdx.z * sO;
    const int r0 = blockIdx.y * 32, c0 = blockIdx.x * 32;
    const int tx = threadIdx.x, ty = threadIdx.y;
#pragma unroll
    for (int j = ty; j < 32; j += 8)
        t[j][tx] = in[(size_t)(r0 + j) * C + c0 + tx];
    __syncthreads();
#pragma unroll
    for (int j = ty; j < 32; j += 8) {
        const float v = t[tx][j];
        const bf16 h = __float2bfloat16(v);
        ohi[(size_t)(c0 + j) * R + r0 + tx] = h;
        olo[(size_t)(c0 + j) * R + r0 + tx] = __float2bfloat16(v - __bfloat162float(h));
    }
}

// ---------------- w = Wk . bq  (w[d] = sum_e Wk[d,e] bq[e]) -----------------
__global__ __launch_bounds__(256) void matvec_w(
    const float* __restrict__ Wk, const float* __restrict__ bq, float* __restrict__ w)
{
    const int d = blockIdx.x * 8 + (threadIdx.x >> 5);   // row
    const int lane = threadIdx.x & 31;
    float s = 0.f;
    for (int e = lane; e < DQ; e += 32) s += Wk[(size_t)d * DQ + e] * bq[e];
#pragma unroll
    for (int o = 16; o > 0; o >>= 1) s += __shfl_xor_sync(0xFFFFFFFFu, s, o);
    if (lane == 0) w[d] = s;
}

// ---------------- vvec[r] = key[r,:] . w  ----------------------------------
__global__ __launch_bounds__(256) void matvec_v(
    const float* __restrict__ key, const float* __restrict__ w, float* __restrict__ vvec)
{
    const int r = blockIdx.x * 8 + (threadIdx.x >> 5);
    const int lane = threadIdx.x & 31;
    float s = 0.f;
    for (int d = lane; d < DK; d += 32) s += key[(size_t)r * DK + d] * w[d];
#pragma unroll
    for (int o = 16; o > 0; o >>= 1) s += __shfl_xor_sync(0xFFFFFFFFu, s, o);
    if (lane == 0) vvec[r] = s;
}

// ---------------- softmax rows (+column bias) -> bf16 hi/lo probs -----------
__global__ __launch_bounds__(256) void softmax_split(
    const float* __restrict__ S, const float* __restrict__ vvec,
    bf16* __restrict__ Phi, bf16* __restrict__ Plo)
{
    __shared__ float red[8];
    const size_t row = blockIdx.x;
    const float* p = S + row * (size_t)SLK;
    const float* vv = vvec + (row >> 11) * (size_t)SLK;   // batch = row/2048
    const int tid = threadIdx.x;

    float xv[8];
#pragma unroll
    for (int j = 0; j < 8; j++) xv[j] = p[tid + j * 256] + vv[tid + j * 256];

    float m = -1e30f;
#pragma unroll
    for (int j = 0; j < 8; j++) m = fmaxf(m, xv[j]);
#pragma unroll
    for (int o = 16; o > 0; o >>= 1) m = fmaxf(m, __shfl_xor_sync(0xFFFFFFFFu, m, o));
    if ((tid & 31) == 0) red[tid >> 5] = m;
    __syncthreads();
    if (tid < 32) {
        float v = (tid < 8) ? red[tid] : -1e30f;
#pragma unroll
        for (int o = 4; o > 0; o >>= 1) v = fmaxf(v, __shfl_xor_sync(0xFFFFFFFFu, v, o));
        if (tid == 0) red[0] = v;
    }
    __syncthreads();
    m = red[0];
    __syncthreads();

    float s = 0.0f;
#pragma unroll
    for (int j = 0; j < 8; j++) { xv[j] = expf(xv[j] - m); s += xv[j]; }
#pragma unroll
    for (int o = 16; o > 0; o >>= 1) s += __shfl_xor_sync(0xFFFFFFFFu, s, o);
    if ((tid & 31) == 0) red[tid >> 5] = s;
    __syncthreads();
    if (tid < 32) {
        float v = (tid < 8) ? red[tid] : 0.0f;
#pragma unroll
        for (int o = 4; o > 0; o >>= 1) v += __shfl_xor_sync(0xFFFFFFFFu, v, o);
        if (tid == 0) red[0] = v;
    }
    __syncthreads();
    const float inv = 1.0f / red[0];

#pragma unroll
    for (int j = 0; j < 8; j++) {
        const float e = xv[j] * inv;
        const bf16 h = __float2bfloat16(e);
        Phi[row * (size_t)SLK + tid + j * 256] = h;
        Plo[row * (size_t)SLK + tid + j * 256] = __float2bfloat16(e - __bfloat162float(h));
    }
}

// ============================================================================
extern "C" void kernel_launch(void* const* d_in, const int* in_sizes, int n_in,
                              void* d_out, int out_size)
{
    const float* query = (const float*)d_in[0];
    const float* key   = (const float*)d_in[1];
    const float* value = (const float*)d_in[2];
    const float* Wq    = (const float*)d_in[3];
    const float* bq    = (const float*)d_in[4];
    const float* Wk    = (const float*)d_in[5];
    const float* bk    = (const float*)d_in[6];   // cancels in softmax (row-const)
    const float* Wv    = (const float*)d_in[7];
    const float* bv    = (const float*)d_in[8];
    float* out = (float*)d_out;
    (void)bk;

    bf16 *qxh, *qxl, *kxh, *kxl, *wqh, *wql, *wkh, *wkl, *wvth, *wvtl;
    bf16 *vth, *vtl, *mth, *mtl, *th, *tl, *uh, *ul, *ph, *pl;
    float *s, *wbq, *vvec;
    cudaGetSymbolAddress((void**)&qxh, g_qx_hi);  cudaGetSymbolAddress((void**)&qxl, g_qx_lo);
    cudaGetSymbolAddress((void**)&kxh, g_kx_hi);  cudaGetSymbolAddress((void**)&kxl, g_kx_lo);
    cudaGetSymbolAddress((void**)&wqh, g_wq_hi);  cudaGetSymbolAddress((void**)&wql, g_wq_lo);
    cudaGetSymbolAddress((void**)&wkh, g_wk_hi);  cudaGetSymbolAddress((void**)&wkl, g_wk_lo);
    cudaGetSymbolAddress((void**)&wvth, g_wvt_hi); cudaGetSymbolAddress((void**)&wvtl, g_wvt_lo);
    cudaGetSymbolAddress((void**)&vth, g_vt_hi);  cudaGetSymbolAddress((void**)&vtl, g_vt_lo);
    cudaGetSymbolAddress((void**)&mth, g_mt_hi);  cudaGetSymbolAddress((void**)&mtl, g_mt_lo);
    cudaGetSymbolAddress((void**)&th, g_t_hi);    cudaGetSymbolAddress((void**)&tl, g_t_lo);
    cudaGetSymbolAddress((void**)&uh, g_u_hi);    cudaGetSymbolAddress((void**)&ul, g_u_lo);
    cudaGetSymbolAddress((void**)&ph, g_p_hi);    cudaGetSymbolAddress((void**)&pl, g_p_lo);
    cudaGetSymbolAddress((void**)&s, g_s);
    cudaGetSymbolAddress((void**)&wbq, g_wbq);
    cudaGetSymbolAddress((void**)&vvec, g_vvec);

    cudaFuncSetAttribute(gemm_mma<0>, cudaFuncAttributeMaxDynamicSharedMemorySize, GSMEM);
    cudaFuncSetAttribute(gemm_mma<1>, cudaFuncAttributeMaxDynamicSharedMemorySize, GSMEM);

    const dim3 tb(32, 8, 1);

    // ---- splits of raw inputs ----
    convert_split<<<(unsigned)((size_t)MFLAT * DQ / 4 / 256), 256>>>(
        (const float4*)query, (uint2*)qxh, (uint2*)qxl, (size_t)MFLAT * DQ / 4);
    convert_split<<<(unsigned)((size_t)MFLAT * DK / 4 / 256), 256>>>(
        (const float4*)key, (uint2*)kxh, (uint2*)kxl, (size_t)MFLAT * DK / 4);
    convert_split<<<(unsigned)((size_t)DQ * DQ / 4 / 256), 256>>>(
        (const float4*)Wq, (uint2*)wqh, (uint2*)wql, (size_t)DQ * DQ / 4);
    convert_split<<<(unsigned)((size_t)DK * DQ / 4 / 256), 256>>>(
        (const float4*)Wk, (uint2*)wkh, (uint2*)wkl, (size_t)DK * DQ / 4);
    // Wv [512,1024] -> Wv^T [1024,512]
    transpose_split<<<dim3(DQ / 32, DV / 32, 1), tb>>>(Wv, wvth, wvtl, DV, DQ, 0, 0);
    // value [B,2048,512] -> value^T [B,512,2048]
    transpose_split<<<dim3(DV / 32, SLK / 32, BB), tb>>>(
        value, vth, vtl, SLK, DV, (size_t)SLK * DV, (size_t)DV * SLK);

    // ---- bias correction vector (handles bq != 0; bk cancels) ----
    matvec_w<<<DK / 8, 256>>>(Wk, bq, wbq);
    matvec_v<<<MFLAT / 8, 256>>>(key, wbq, vvec);

    // ---- Mt = Wk Wq^T : [512,1024], split out ----
    gemm_mma<1><<<dim3(DQ / 128, DK / 128, 1), 256, GSMEM>>>(
        wkh, wkl, wqh, wql, nullptr, nullptr, mth, mtl, DK, DQ, DQ, 0, 0, 0);

    // ---- T = q Mt^T : [16384,512], split out ----
    gemm_mma<1><<<dim3(DK / 128, MFLAT / 128, 1), 256, GSMEM>>>(
        qxh, qxl, mth, mtl, nullptr, nullptr, th, tl, MFLAT, DK, DQ, 0, 0, 0);

    // ---- S = T key^T per batch : [2048,2048] fp32 ----
    gemm_mma<0><<<dim3(SLK / 128, SLQ / 128, BB), 256, GSMEM>>>(
        th, tl, kxh, kxl, nullptr, s, nullptr, nullptr,
        SLQ, SLK, DK, (size_t)SLQ * DK, (size_t)SLK * DK, (size_t)SLQ * SLK);

    // ---- softmax (+vvec column bias) -> split probs ----
    softmax_split<<<BB * SLQ, 256>>>(s, vvec, ph, pl);

    // ---- U = P value per batch : [2048,512], split out ----
    gemm_mma<1><<<dim3(DV / 128, SLQ / 128, BB), 256, GSMEM>>>(
        ph, pl, vth, vtl, nullptr, nullptr, uh, ul,
        SLQ, DV, SLK, (size_t)SLQ * SLK, (size_t)DV * SLK, (size_t)SLQ * DV);

    // ---- out = U Wv + bv per batch : [2048,1024] fp32 ----
    gemm_mma<0><<<dim3(DQ / 128, SLQ / 128, BB), 256, GSMEM>>>(
        uh, ul, wvth, wvtl, bv, out, nullptr, nullptr,
        SLQ, DQ, DV, (size_t)SLQ * DV, 0, (size_t)SLQ * DQ);
}

// round 5
// speedup vs baseline: 5.1429x; 1.1788x over previous
#include <cuda_runtime.h>
#include <cuda_fp16.h>
#include <cstdint>
#include <math.h>

// ---------------- problem dims ----------------
#define BB 8
#define SLQ 2048
#define SLK 2048
#define DQ 1024
#define DK 512
#define DV 512
#define MFLAT (BB * SLQ)          // 16384

typedef __half f16;

// ---------------- scratch (device globals; allocation-free rule) ------------
__device__ __align__(256) f16 g_qx_hi[(size_t)MFLAT * DQ];
__device__ __align__(256) f16 g_qx_lo[(size_t)MFLAT * DQ];
__device__ __align__(256) f16 g_kx_hi[(size_t)MFLAT * DK];
__device__ __align__(256) f16 g_kx_lo[(size_t)MFLAT * DK];
__device__ __align__(256) f16 g_wq_hi[(size_t)DQ * DQ];
__device__ __align__(256) f16 g_wq_lo[(size_t)DQ * DQ];
__device__ __align__(256) f16 g_wk_hi[(size_t)DK * DQ];
__device__ __align__(256) f16 g_wk_lo[(size_t)DK * DQ];
__device__ __align__(256) f16 g_wvt_hi[(size_t)DQ * DV];      // Wv^T [1024,512]
__device__ __align__(256) f16 g_wvt_lo[(size_t)DQ * DV];
__device__ __align__(256) f16 g_vt_hi[(size_t)BB * DV * SLK]; // value^T [B,512,2048]
__device__ __align__(256) f16 g_vt_lo[(size_t)BB * DV * SLK];
__device__ __align__(256) f16 g_mt_hi[(size_t)DK * DQ];       // Mt = Wk Wq^T
__device__ __align__(256) f16 g_mt_lo[(size_t)DK * DQ];
__device__ __align__(256) f16 g_t_hi[(size_t)MFLAT * DK];     // T = q Mt^T (hi only)
__device__ __align__(256) f16 g_u_hi[(size_t)MFLAT * DV];     // U = P v
__device__ __align__(256) f16 g_u_lo[(size_t)MFLAT * DV];
__device__ __align__(256) float g_s[(size_t)BB * SLQ * SLK];  // scores fp32
__device__ __align__(256) f16 g_p_hi[(size_t)BB * SLQ * SLK]; // probs (hi only)
__device__ __align__(256) float g_wbq[DK];
__device__ __align__(256) float g_vvec[MFLAT];

// ---------------- small helpers ----------------
__device__ __forceinline__ uint32_t smem_u32(const void* p) {
    uint32_t a;
    asm("{ .reg .u64 t; cvta.to.shared.u64 t, %1; cvt.u32.u64 %0, t; }" : "=r"(a) : "l"(p));
    return a;
}
// pack: low half <- lo_f, high half <- hi_f
__device__ __forceinline__ uint32_t packh(float hi_f, float lo_f) {
    uint32_t r;
    asm("cvt.rn.f16x2.f32 %0, %1, %2;" : "=r"(r) : "f"(hi_f), "f"(lo_f));
    return r;
}
__device__ __forceinline__ float2 h2f(uint32_t p) {
    __half2 h = *reinterpret_cast<__half2*>(&p);
    return __half22float2(h);
}
__device__ __forceinline__ void cp16(uint32_t dst, const void* src) {
    asm volatile("cp.async.cg.shared.global [%0], [%1], 16;" :: "r"(dst), "l"(src));
}
__device__ __forceinline__ void ldm4(uint32_t (&r)[4], uint32_t a) {
    asm volatile("ldmatrix.sync.aligned.m8n8.x4.shared.b16 {%0,%1,%2,%3}, [%4];"
                 : "=r"(r[0]), "=r"(r[1]), "=r"(r[2]), "=r"(r[3]) : "r"(a));
}
__device__ __forceinline__ void mma16816(float* d, const uint32_t* a, uint32_t b0, uint32_t b1) {
    asm volatile("mma.sync.aligned.m16n8k16.row.col.f32.f16.f16.f32 "
                 "{%0,%1,%2,%3}, {%4,%5,%6,%7}, {%8,%9}, {%0,%1,%2,%3};"
                 : "+f"(d[0]), "+f"(d[1]), "+f"(d[2]), "+f"(d[3])
                 : "r"(a[0]), "r"(a[1]), "r"(a[2]), "r"(a[3]), "r"(b0), "r"(b1));
}

// ---------------- GEMM: C[M,N] = A[M,K] * B[N,K]^T, fp16 split, fp32 acc -----
// PASSES=3: tiles {Ahi, Alo, Bhi, Blo}, products AhBh + AhBl + AlBh.
// PASSES=2: tiles {Ahi, Bhi, Blo},      products AhBh + AhBl.   (A single fp16)
// MODE 0: fp32 out (+bias). MODE 1: split f16 hi/lo out. MODE 2: f16 hi out.
#define ROWB   80
#define TILEB  (128 * ROWB)

template <int PASSES, int MODE>
__global__ __launch_bounds__(256, 2) void gemm_mma(
    const f16* __restrict__ Ahi, const f16* __restrict__ Alo,
    const f16* __restrict__ Bhi, const f16* __restrict__ Blo,
    const float* __restrict__ bias,
    float* __restrict__ Cf, f16* __restrict__ Chi, f16* __restrict__ Clo,
    int M, int N, int K, size_t sA, size_t sB, size_t sC)
{
    constexpr int NT = PASSES + 1;           // tiles per stage
    constexpr int STAGE = NT * TILEB;
    constexpr int T_AL = 1;                  // valid when PASSES==3
    constexpr int T_BH = (PASSES == 3) ? 2 : 1;
    constexpr int T_BL = (PASSES == 3) ? 3 : 2;

    extern __shared__ char smem[];
    const uint32_t sb = smem_u32(smem);
    const int tid = threadIdx.x, wid = tid >> 5, lane = tid & 31;
    const int bz = blockIdx.z;
    const int bm = blockIdx.y * 128, bn = blockIdx.x * 128;

    const f16* src[NT];
    src[0] = Ahi + (size_t)bz * sA + (size_t)bm * K;
    if (PASSES == 3) {
        src[1] = Alo + (size_t)bz * sA + (size_t)bm * K;
        src[2] = Bhi + (size_t)bz * sB + (size_t)bn * K;
        src[3] = Blo + (size_t)bz * sB + (size_t)bn * K;
    } else {
        src[1] = Bhi + (size_t)bz * sB + (size_t)bn * K;
        src[2] = Blo + (size_t)bz * sB + (size_t)bn * K;
    }

    const int wm = wid & 3, wn = wid >> 2;   // warp tile 32(M) x 64(N)
    const uint32_t a_l = (uint32_t)((wm * 32 + (lane & 7) + ((lane >> 3) & 1) * 8) * ROWB
                                    + ((lane >> 4) & 1) * 16);
    const uint32_t b_l = (uint32_t)((wn * 64 + (lane & 7) + ((lane >> 4) & 1) * 8) * ROWB
                                    + ((lane >> 3) & 1) * 16);

    float acc[2][8][4];
#pragma unroll
    for (int m = 0; m < 2; m++)
#pragma unroll
        for (int n = 0; n < 8; n++)
#pragma unroll
            for (int j = 0; j < 4; j++) acc[m][n][j] = 0.0f;

    const int nc = K >> 5;

    auto load_stage = [&](int c, int stage) {
        const int k0 = c << 5;
#pragma unroll
        for (int t = 0; t < 2 * NT; t++) {
            const int idx = tid + t * 256;
            const int tile = idx >> 9;
            const int r = (idx >> 2) & 127;
            const int ch = idx & 3;
            cp16(sb + stage * STAGE + tile * TILEB + r * ROWB + ch * 16,
                 src[tile] + (size_t)r * K + k0 + ch * 8);
        }
        asm volatile("cp.async.commit_group;" ::: "memory");
    };

    load_stage(0, 0);

    for (int c = 0; c < nc; c++) {
        const int stage = c & 1;
        if (c + 1 < nc) {
            load_stage(c + 1, stage ^ 1);
            asm volatile("cp.async.wait_group 1;" ::: "memory");
        } else {
            asm volatile("cp.async.wait_group 0;" ::: "memory");
        }
        __syncthreads();

        const uint32_t base = sb + stage * STAGE;
#pragma unroll
        for (int ks = 0; ks < 2; ks++) {
            const uint32_t koff = ks * 32;
            uint32_t ah[2][4], al[2][4];
            ldm4(ah[0], base + a_l + koff);
            ldm4(ah[1], base + a_l + koff + 16 * ROWB);
            if (PASSES == 3) {
                ldm4(al[0], base + T_AL * TILEB + a_l + koff);
                ldm4(al[1], base + T_AL * TILEB + a_l + koff + 16 * ROWB);
            }
#pragma unroll
            for (int g = 0; g < 4; g++) {
                uint32_t bh[4], bl[4];
                ldm4(bh, base + T_BH * TILEB + b_l + koff + g * 16 * ROWB);
                ldm4(bl, base + T_BL * TILEB + b_l + koff + g * 16 * ROWB);
#pragma unroll
                for (int m = 0; m < 2; m++) {
                    mma16816(acc[m][2 * g],     ah[m], bh[0], bh[1]);
                    mma16816(acc[m][2 * g + 1], ah[m], bh[2], bh[3]);
                    mma16816(acc[m][2 * g],     ah[m], bl[0], bl[1]);
                    mma16816(acc[m][2 * g + 1], ah[m], bl[2], bl[3]);
                    if (PASSES == 3) {
                        mma16816(acc[m][2 * g],     al[m], bh[0], bh[1]);
                        mma16816(acc[m][2 * g + 1], al[m], bh[2], bh[3]);
                    }
                }
            }
        }
        __syncthreads();
    }

    // ---- epilogue ----
    const int row0 = bm + wm * 32 + (lane >> 2);
    const int col0 = bn + wn * 64 + (lane & 3) * 2;
#pragma unroll
    for (int m = 0; m < 2; m++) {
#pragma unroll
        for (int nt = 0; nt < 8; nt++) {
            const int r = row0 + m * 16;
            const int cc = col0 + nt * 8;
            float b0 = 0.f, b1 = 0.f;
            if (bias) { b0 = bias[cc]; b1 = bias[cc + 1]; }
            const float x0 = acc[m][nt][0] + b0, x1 = acc[m][nt][1] + b1;
            const float y0 = acc[m][nt][2] + b0, y1 = acc[m][nt][3] + b1;
            if (MODE == 0) {
                float* p0 = Cf + (size_t)bz * sC + (size_t)r * N + cc;
                float* p1 = Cf + (size_t)bz * sC + (size_t)(r + 8) * N + cc;
                *(float2*)p0 = make_float2(x0, x1);
                *(float2*)p1 = make_float2(y0, y1);
            } else if (MODE == 2) {
                *(uint32_t*)(Chi + (size_t)bz * sC + (size_t)r * N + cc) = packh(x1, x0);
                *(uint32_t*)(Chi + (size_t)bz * sC + (size_t)(r + 8) * N + cc) = packh(y1, y0);
            } else {
                const uint32_t hx = packh(x1, x0);
                const float2 fx = h2f(hx);
                const uint32_t lx = packh(x1 - fx.y, x0 - fx.x);
                const uint32_t hy = packh(y1, y0);
                const float2 fy = h2f(hy);
                const uint32_t ly = packh(y1 - fy.y, y0 - fy.x);
                *(uint32_t*)(Chi + (size_t)bz * sC + (size_t)r * N + cc) = hx;
                *(uint32_t*)(Clo + (size_t)bz * sC + (size_t)r * N + cc) = lx;
                *(uint32_t*)(Chi + (size_t)bz * sC + (size_t)(r + 8) * N + cc) = hy;
                *(uint32_t*)(Clo + (size_t)bz * sC + (size_t)(r + 8) * N + cc) = ly;
            }
        }
    }
}

// ---------------- fp32 -> fp16 hi/lo split (flat) ----------------
__global__ __launch_bounds__(256) void convert_split(
    const float4* __restrict__ in, uint2* __restrict__ hi, uint2* __restrict__ lo, size_t n4)
{
    size_t i = (size_t)blockIdx.x * blockDim.x + threadIdx.x;
    if (i >= n4) return;
    const float4 v = in[i];
    const uint32_t h01 = packh(v.y, v.x);
    const uint32_t h23 = packh(v.w, v.z);
    const float2 f01 = h2f(h01), f23 = h2f(h23);
    const uint32_t l01 = packh(v.y - f01.y, v.x - f01.x);
    const uint32_t l23 = packh(v.w - f23.y, v.z - f23.x);
    hi[i] = make_uint2(h01, h23);
    lo[i] = make_uint2(l01, l23);
}

// ---------------- fp32 [R,C] -> transposed f16 hi/lo [C,R], batched --------
__global__ __launch_bounds__(256) void transpose_split(
    const float* __restrict__ in, f16* __restrict__ ohi, f16* __restrict__ olo,
    int R, int C, size_t sI, size_t sO)
{
    __shared__ float t[32][33];
    in  += (size_t)blockIdx.z * sI;
    ohi += (size_t)blockIdx.z * sO;
    olo += (size_t)blockIdx.z * sO;
    const int r0 = blockIdx.y * 32, c0 = blockIdx.x * 32;
    const int tx = threadIdx.x, ty = threadIdx.y;
#pragma unroll
    for (int j = ty; j < 32; j += 8)
        t[j][tx] = in[(size_t)(r0 + j) * C + c0 + tx];
    __syncthreads();
#pragma unroll
    for (int j = ty; j < 32; j += 8) {
        const float v = t[tx][j];
        const f16 h = __float2half_rn(v);
        ohi[(size_t)(c0 + j) * R + r0 + tx] = h;
        olo[(size_t)(c0 + j) * R + r0 + tx] = __float2half_rn(v - __half2float(h));
    }
}

// ---------------- w = Wk . bq ----------------
__global__ __launch_bounds__(256) void matvec_w(
    const float* __restrict__ Wk, const float* __restrict__ bq, float* __restrict__ w)
{
    const int d = blockIdx.x * 8 + (threadIdx.x >> 5);
    const int lane = threadIdx.x & 31;
    float s = 0.f;
    for (int e = lane; e < DQ; e += 32) s += Wk[(size_t)d * DQ + e] * bq[e];
#pragma unroll
    for (int o = 16; o > 0; o >>= 1) s += __shfl_xor_sync(0xFFFFFFFFu, s, o);
    if (lane == 0) w[d] = s;
}

// ---------------- vvec[r] = key[r,:] . w ----------------
__global__ __launch_bounds__(256) void matvec_v(
    const float* __restrict__ key, const float* __restrict__ w, float* __restrict__ vvec)
{
    const int r = blockIdx.x * 8 + (threadIdx.x >> 5);
    const int lane = threadIdx.x & 31;
    float s = 0.f;
    for (int d = lane; d < DK; d += 32) s += key[(size_t)r * DK + d] * w[d];
#pragma unroll
    for (int o = 16; o > 0; o >>= 1) s += __shfl_xor_sync(0xFFFFFFFFu, s, o);
    if (lane == 0) vvec[r] = s;
}

// ---------------- softmax rows (+column bias) -> f16 probs (hi only) --------
__global__ __launch_bounds__(256) void softmax_ph(
    const float* __restrict__ S, const float* __restrict__ vvec, f16* __restrict__ Phi)
{
    __shared__ float red[8];
    const size_t row = blockIdx.x;
    const float* p = S + row * (size_t)SLK;
    const float* vv = vvec + (row >> 11) * (size_t)SLK;
    const int tid = threadIdx.x;

    float xv[8];
#pragma unroll
    for (int j = 0; j < 8; j++) xv[j] = p[tid + j * 256] + vv[tid + j * 256];

    float m = -1e30f;
#pragma unroll
    for (int j = 0; j < 8; j++) m = fmaxf(m, xv[j]);
#pragma unroll
    for (int o = 16; o > 0; o >>= 1) m = fmaxf(m, __shfl_xor_sync(0xFFFFFFFFu, m, o));
    if ((tid & 31) == 0) red[tid >> 5] = m;
    __syncthreads();
    if (tid < 32) {
        float v = (tid < 8) ? red[tid] : -1e30f;
#pragma unroll
        for (int o = 4; o > 0; o >>= 1) v = fmaxf(v, __shfl_xor_sync(0xFFFFFFFFu, v, o));
        if (tid == 0) red[0] = v;
    }
    __syncthreads();
    m = red[0];
    __syncthreads();

    float s = 0.0f;
#pragma unroll
    for (int j = 0; j < 8; j++) { xv[j] = expf(xv[j] - m); s += xv[j]; }
#pragma unroll
    for (int o = 16; o > 0; o >>= 1) s += __shfl_xor_sync(0xFFFFFFFFu, s, o);
    if ((tid & 31) == 0) red[tid >> 5] = s;
    __syncthreads();
    if (tid < 32) {
        float v = (tid < 8) ? red[tid] : 0.0f;
#pragma unroll
        for (int o = 4; o > 0; o >>= 1) v += __shfl_xor_sync(0xFFFFFFFFu, v, o);
        if (tid == 0) red[0] = v;
    }
    __syncthreads();
    const float inv = 1.0f / red[0];

#pragma unroll
    for (int j = 0; j < 8; j++)
        Phi[row * (size_t)SLK + tid + j * 256] = __float2half_rn(xv[j] * inv);
}

// ============================================================================
extern "C" void kernel_launch(void* const* d_in, const int* in_sizes, int n_in,
                              void* d_out, int out_size)
{
    const float* query = (const float*)d_in[0];
    const float* key   = (const float*)d_in[1];
    const float* value = (const float*)d_in[2];
    const float* Wq    = (const float*)d_in[3];
    const float* bq    = (const float*)d_in[4];
    const float* Wk    = (const float*)d_in[5];
    const float* bk    = (const float*)d_in[6];   // cancels in softmax (row-const)
    const float* Wv    = (const float*)d_in[7];
    const float* bv    = (const float*)d_in[8];
    float* out = (float*)d_out;
    (void)bk;

    f16 *qxh, *qxl, *kxh, *kxl, *wqh, *wql, *wkh, *wkl, *wvth, *wvtl;
    f16 *vth, *vtl, *mth, *mtl, *th, *uh, *ul, *ph;
    float *s, *wbq, *vvec;
    cudaGetSymbolAddress((void**)&qxh, g_qx_hi);  cudaGetSymbolAddress((void**)&qxl, g_qx_lo);
    cudaGetSymbolAddress((void**)&kxh, g_kx_hi);  cudaGetSymbolAddress((void**)&kxl, g_kx_lo);
    cudaGetSymbolAddress((void**)&wqh, g_wq_hi);  cudaGetSymbolAddress((void**)&wql, g_wq_lo);
    cudaGetSymbolAddress((void**)&wkh, g_wk_hi);  cudaGetSymbolAddress((void**)&wkl, g_wk_lo);
    cudaGetSymbolAddress((void**)&wvth, g_wvt_hi); cudaGetSymbolAddress((void**)&wvtl, g_wvt_lo);
    cudaGetSymbolAddress((void**)&vth, g_vt_hi);  cudaGetSymbolAddress((void**)&vtl, g_vt_lo);
    cudaGetSymbolAddress((void**)&mth, g_mt_hi);  cudaGetSymbolAddress((void**)&mtl, g_mt_lo);
    cudaGetSymbolAddress((void**)&th, g_t_hi);
    cudaGetSymbolAddress((void**)&uh, g_u_hi);    cudaGetSymbolAddress((void**)&ul, g_u_lo);
    cudaGetSymbolAddress((void**)&ph, g_p_hi);
    cudaGetSymbolAddress((void**)&s, g_s);
    cudaGetSymbolAddress((void**)&wbq, g_wbq);
    cudaGetSymbolAddress((void**)&vvec, g_vvec);

    const int SM3 = 2 * 4 * TILEB;   // 81920
    const int SM2 = 2 * 3 * TILEB;   // 61440
    cudaFuncSetAttribute(gemm_mma<3, 0>, cudaFuncAttributeMaxDynamicSharedMemorySize, SM3);
    cudaFuncSetAttribute(gemm_mma<3, 1>, cudaFuncAttributeMaxDynamicSharedMemorySize, SM3);
    cudaFuncSetAttribute(gemm_mma<3, 2>, cudaFuncAttributeMaxDynamicSharedMemorySize, SM3);
    cudaFuncSetAttribute(gemm_mma<2, 0>, cudaFuncAttributeMaxDynamicSharedMemorySize, SM2);
    cudaFuncSetAttribute(gemm_mma<2, 1>, cudaFuncAttributeMaxDynamicSharedMemorySize, SM2);

    const dim3 tb(32, 8, 1);

    // ---- splits of raw inputs (fp16 hi/lo) ----
    convert_split<<<(unsigned)((size_t)MFLAT * DQ / 4 / 256), 256>>>(
        (const float4*)query, (uint2*)qxh, (uint2*)qxl, (size_t)MFLAT * DQ / 4);
    convert_split<<<(unsigned)((size_t)MFLAT * DK / 4 / 256), 256>>>(
        (const float4*)key, (uint2*)kxh, (uint2*)kxl, (size_t)MFLAT * DK / 4);
    convert_split<<<(unsigned)((size_t)DQ * DQ / 4 / 256), 256>>>(
        (const float4*)Wq, (uint2*)wqh, (uint2*)wql, (size_t)DQ * DQ / 4);
    convert_split<<<(unsigned)((size_t)DK * DQ / 4 / 256), 256>>>(
        (const float4*)Wk, (uint2*)wkh, (uint2*)wkl, (size_t)DK * DQ / 4);
    transpose_split<<<dim3(DQ / 32, DV / 32, 1), tb>>>(Wv, wvth, wvtl, DV, DQ, 0, 0);
    transpose_split<<<dim3(DV / 32, SLK / 32, BB), tb>>>(
        value, vth, vtl, SLK, DV, (size_t)SLK * DV, (size_t)DV * SLK);

    // ---- bias correction vector (bq path; bk cancels) ----
    matvec_w<<<DK / 8, 256>>>(Wk, bq, wbq);
    matvec_v<<<MFLAT / 8, 256>>>(key, wbq, vvec);

    // ---- Mt = Wk Wq^T : [512,1024], 3-pass, split out ----
    gemm_mma<3, 1><<<dim3(DQ / 128, DK / 128, 1), 256, SM3>>>(
        wkh, wkl, wqh, wql, nullptr, nullptr, mth, mtl, DK, DQ, DQ, 0, 0, 0);

    // ---- T = q Mt^T : [16384,512], 3-pass, f16-hi out ----
    gemm_mma<3, 2><<<dim3(DK / 128, MFLAT / 128, 1), 256, SM3>>>(
        qxh, qxl, mth, mtl, nullptr, nullptr, th, nullptr, MFLAT, DK, DQ, 0, 0, 0);

    // ---- S = T key^T per batch : 2-pass (A = Th single, B = k split), fp32 out ----
    gemm_mma<2, 0><<<dim3(SLK / 128, SLQ / 128, BB), 256, SM2>>>(
        th, nullptr, kxh, kxl, nullptr, s, nullptr, nullptr,
        SLQ, SLK, DK, (size_t)SLQ * DK, (size_t)SLK * DK, (size_t)SLQ * SLK);

    // ---- softmax (+vvec column bias) -> f16 probs ----
    softmax_ph<<<BB * SLQ, 256>>>(s, vvec, ph);

    // ---- U = P value per batch : 2-pass (A = Ph single, B = v split), split out ----
    gemm_mma<2, 1><<<dim3(DV / 128, SLQ / 128, BB), 256, SM2>>>(
        ph, nullptr, vth, vtl, nullptr, nullptr, uh, ul,
        SLQ, DV, SLK, (size_t)SLQ * SLK, (size_t)DV * SLK, (size_t)SLQ * DV);

    // ---- out = U Wv + bv per batch : 3-pass, fp32 out ----
    gemm_mma<3, 0><<<dim3(DQ / 128, SLQ / 128, BB), 256, SM3>>>(
        uh, ul, wvth, wvtl, bv, out, nullptr, nullptr,
        SLQ, DQ, DV, (size_t)SLQ * DV, 0, (size_t)SLQ * DQ);
}

// round 6
// speedup vs baseline: 5.2923x; 1.0290x over previous
#include <cuda_runtime.h>
#include <cuda_fp16.h>
#include <cstdint>
#include <math.h>

// ---------------- problem dims ----------------
#define BB 8
#define SLQ 2048
#define SLK 2048
#define DQ 1024
#define DK 512
#define DV 512
#define MFLAT (BB * SLQ)          // 16384

typedef __half f16;

// ---------------- scratch (device globals; allocation-free rule) ------------
__device__ __align__(256) f16 g_wq_hi[(size_t)DQ * DQ];
__device__ __align__(256) f16 g_wq_lo[(size_t)DQ * DQ];
__device__ __align__(256) f16 g_wk_hi[(size_t)DK * DQ];
__device__ __align__(256) f16 g_wk_lo[(size_t)DK * DQ];
__device__ __align__(256) f16 g_wvt_hi[(size_t)DQ * DV];      // Wv^T [1024,512]
__device__ __align__(256) f16 g_wvt_lo[(size_t)DQ * DV];
__device__ __align__(256) f16 g_vt_hi[(size_t)BB * DV * SLK]; // value^T [B,512,2048]
__device__ __align__(256) f16 g_vt_lo[(size_t)BB * DV * SLK];
__device__ __align__(256) f16 g_mt_hi[(size_t)DK * DQ];       // Mt = Wk Wq^T
__device__ __align__(256) f16 g_mt_lo[(size_t)DK * DQ];
__device__ __align__(256) f16 g_t_hi[(size_t)MFLAT * DK];     // T = q Mt^T (hi only)
__device__ __align__(256) f16 g_u_hi[(size_t)MFLAT * DV];     // U = P v
__device__ __align__(256) f16 g_u_lo[(size_t)MFLAT * DV];
__device__ __align__(256) float g_s[(size_t)BB * SLQ * SLK];  // scores fp32
__device__ __align__(256) f16 g_p_hi[(size_t)BB * SLQ * SLK]; // probs (hi only)
__device__ __align__(256) float g_wbq[DK];
__device__ __align__(256) float g_vvec[MFLAT];

// ---------------- small helpers ----------------
__device__ __forceinline__ uint32_t smem_u32(const void* p) {
    uint32_t a;
    asm("{ .reg .u64 t; cvta.to.shared.u64 t, %1; cvt.u32.u64 %0, t; }" : "=r"(a) : "l"(p));
    return a;
}
// pack: low half <- lo_f, high half <- hi_f
__device__ __forceinline__ uint32_t packh(float hi_f, float lo_f) {
    uint32_t r;
    asm("cvt.rn.f16x2.f32 %0, %1, %2;" : "=r"(r) : "f"(hi_f), "f"(lo_f));
    return r;
}
__device__ __forceinline__ float2 h2f(uint32_t p) {
    __half2 h = *reinterpret_cast<__half2*>(&p);
    return __half22float2(h);
}
__device__ __forceinline__ void cp16(uint32_t dst, const void* src) {
    asm volatile("cp.async.cg.shared.global [%0], [%1], 16;" :: "r"(dst), "l"(src));
}
__device__ __forceinline__ void ldm4(uint32_t (&r)[4], uint32_t a) {
    asm volatile("ldmatrix.sync.aligned.m8n8.x4.shared.b16 {%0,%1,%2,%3}, [%4];"
                 : "=r"(r[0]), "=r"(r[1]), "=r"(r[2]), "=r"(r[3]) : "r"(a));
}
__device__ __forceinline__ void mma16816(float* d, const uint32_t* a, uint32_t b0, uint32_t b1) {
    asm volatile("mma.sync.aligned.m16n8k16.row.col.f32.f16.f16.f32 "
                 "{%0,%1,%2,%3}, {%4,%5,%6,%7}, {%8,%9}, {%0,%1,%2,%3};"
                 : "+f"(d[0]), "+f"(d[1]), "+f"(d[2]), "+f"(d[3])
                 : "r"(a[0]), "r"(a[1]), "r"(a[2]), "r"(a[3]), "r"(b0), "r"(b1));
}

// ---------------- GEMM: C[M,N] = A[M,K] * B[N,K]^T, fp16 split, fp32 acc -----
// PASSES=3: tiles {Ah, Al, Bh, Bl}, products AhBh + AhBl + AlBh.
// PASSES=2: tiles {Ah, Bh, Bl},     products AhBh + AhBl.   (A single fp16)
// AF32: A side comes from fp32, split in-kernel (PASSES=3 only here).
// BF32: B side comes from fp32, split in-kernel (PASSES=2 only here).
// MODE 0: fp32 out (+bias). MODE 1: split f16 hi/lo out. MODE 2: f16 hi out.
#define ROWB   80
#define TILEB  (128 * ROWB)

template <int PASSES, int MODE, int AF32, int BF32>
__global__ __launch_bounds__(256, 2) void gemm_mma(
    const f16* __restrict__ Ahi, const f16* __restrict__ Alo,
    const float* __restrict__ A32,
    const f16* __restrict__ Bhi, const f16* __restrict__ Blo,
    const float* __restrict__ B32,
    const float* __restrict__ bias,
    float* __restrict__ Cf, f16* __restrict__ Chi, f16* __restrict__ Clo,
    int M, int N, int K, size_t sA, size_t sB, size_t sC)
{
    constexpr int NT = PASSES + 1;            // tiles per stage
    constexpr int STAGE = NT * TILEB;
    constexpr bool F32 = (AF32 || BF32);
    constexpr int SCRO = 2 * STAGE;           // fp32 scratch offset (single buffer)
    constexpr int T_AL = 1;
    constexpr int T_BH = (PASSES == 3) ? 2 : 1;
    constexpr int T_BL = (PASSES == 3) ? 3 : 2;
    constexpr int NF16 = (PASSES == 3) ? (AF32 ? 2 : 4) : (BF32 ? 1 : 3);
    constexpr int T32H = AF32 ? 0 : T_BH;     // dst tiles of the fp32 side
    constexpr int T32L = AF32 ? T_AL : T_BL;

    extern __shared__ char smem[];
    const uint32_t sb = smem_u32(smem);
    const int tid = threadIdx.x, wid = tid >> 5, lane = tid & 31;
    const int bz = blockIdx.z;
    const int bm = blockIdx.y * 128, bn = blockIdx.x * 128;

    // f16 tile sources + destination tile slots
    const f16* s16[NF16 ? NF16 : 1];
    int d16[NF16 ? NF16 : 1];
    if (PASSES == 3) {
        if (AF32) {
            s16[0] = Bhi + (size_t)bz * sB + (size_t)bn * K; d16[0] = T_BH;
            s16[1] = Blo + (size_t)bz * sB + (size_t)bn * K; d16[1] = T_BL;
        } else {
            s16[0] = Ahi + (size_t)bz * sA + (size_t)bm * K; d16[0] = 0;
            s16[1] = Alo + (size_t)bz * sA + (size_t)bm * K; d16[1] = T_AL;
            s16[2] = Bhi + (size_t)bz * sB + (size_t)bn * K; d16[2] = T_BH;
            s16[3] = Blo + (size_t)bz * sB + (size_t)bn * K; d16[3] = T_BL;
        }
    } else {
        s16[0] = Ahi + (size_t)bz * sA + (size_t)bm * K; d16[0] = 0;
        if (!BF32) {
            s16[1] = Bhi + (size_t)bz * sB + (size_t)bn * K; d16[1] = T_BH;
            s16[2] = Blo + (size_t)bz * sB + (size_t)bn * K; d16[2] = T_BL;
        }
    }
    const float* s32 = AF32 ? (A32 + (size_t)bz * sA + (size_t)bm * K)
                            : (BF32 ? (B32 + (size_t)bz * sB + (size_t)bn * K) : nullptr);

    const int wm = wid & 3, wn = wid >> 2;    // warp tile 32(M) x 64(N)
    const uint32_t a_l = (uint32_t)((wm * 32 + (lane & 7) + ((lane >> 3) & 1) * 8) * ROWB
                                    + ((lane >> 4) & 1) * 16);
    const uint32_t b_l = (uint32_t)((wn * 64 + (lane & 7) + ((lane >> 4) & 1) * 8) * ROWB
                                    + ((lane >> 3) & 1) * 16);

    float acc[2][8][4];
#pragma unroll
    for (int m = 0; m < 2; m++)
#pragma unroll
        for (int n = 0; n < 8; n++)
#pragma unroll
            for (int j = 0; j < 4; j++) acc[m][n][j] = 0.0f;

    const int nc = K >> 5;

    auto load_stage = [&](int c, int stage) {
        const int k0 = c << 5;
#pragma unroll
        for (int t = 0; t < 2 * NF16; t++) {
            const int idx = tid + t * 256;
            const int tile = idx >> 9;
            const int r = (idx >> 2) & 127;
            const int ch = idx & 3;
            cp16(sb + stage * STAGE + d16[tile] * TILEB + r * ROWB + ch * 16,
                 s16[tile] + (size_t)r * K + k0 + ch * 8);
        }
        if (F32) {
#pragma unroll
            for (int t = 0; t < 4; t++) {
                const int idx = tid + t * 256;
                const int r = idx >> 3;          // 0..127
                const int c4 = idx & 7;          // 4-float chunk
                cp16(sb + SCRO + r * 128 + c4 * 16,
                     s32 + (size_t)r * K + k0 + c4 * 4);
            }
        }
        asm volatile("cp.async.commit_group;" ::: "memory");
    };

    auto convert_stage = [&](int stage) {
#pragma unroll
        for (int t = 0; t < 4; t++) {
            const int idx = tid + t * 256;
            const int r = idx >> 3;
            const int c4 = idx & 7;
            const float4 v = *(const float4*)(smem + SCRO + r * 128 + c4 * 16);
            const uint32_t h01 = packh(v.y, v.x);
            const uint32_t h23 = packh(v.w, v.z);
            const float2 f01 = h2f(h01), f23 = h2f(h23);
            const uint32_t l01 = packh(v.y - f01.y, v.x - f01.x);
            const uint32_t l23 = packh(v.w - f23.y, v.z - f23.x);
            const int off = stage * STAGE + r * ROWB + c4 * 8;
            *(uint2*)(smem + off + T32H * TILEB) = make_uint2(h01, h23);
            *(uint2*)(smem + off + T32L * TILEB) = make_uint2(l01, l23);
        }
    };

    auto compute_stage = [&](int stage) {
        const uint32_t base = sb + stage * STAGE;
#pragma unroll
        for (int ks = 0; ks < 2; ks++) {
            const uint32_t koff = ks * 32;
            uint32_t ah[2][4], al[2][4];
            ldm4(ah[0], base + a_l + koff);
            ldm4(ah[1], base + a_l + koff + 16 * ROWB);
            if (PASSES == 3) {
                ldm4(al[0], base + T_AL * TILEB + a_l + koff);
                ldm4(al[1], base + T_AL * TILEB + a_l + koff + 16 * ROWB);
            }
#pragma unroll
            for (int g = 0; g < 4; g++) {
                uint32_t bh[4], bl[4];
                ldm4(bh, base + T_BH * TILEB + b_l + koff + g * 16 * ROWB);
                ldm4(bl, base + T_BL * TILEB + b_l + koff + g * 16 * ROWB);
#pragma unroll
                for (int m = 0; m < 2; m++) {
                    mma16816(acc[m][2 * g],     ah[m], bh[0], bh[1]);
                    mma16816(acc[m][2 * g + 1], ah[m], bh[2], bh[3]);
                    mma16816(acc[m][2 * g],     ah[m], bl[0], bl[1]);
                    mma16816(acc[m][2 * g + 1], ah[m], bl[2], bl[3]);
                    if (PASSES == 3) {
                        mma16816(acc[m][2 * g],     al[m], bh[0], bh[1]);
                        mma16816(acc[m][2 * g + 1], al[m], bh[2], bh[3]);
                    }
                }
            }
        }
    };

    load_stage(0, 0);

    for (int c = 0; c < nc; c++) {
        const int stage = c & 1;
        if (F32) {
            asm volatile("cp.async.wait_group 0;" ::: "memory");
            __syncthreads();
            convert_stage(stage);
            __syncthreads();
            if (c + 1 < nc) load_stage(c + 1, stage ^ 1);
            compute_stage(stage);
            // no trailing sync: next iter's top sync guards reuse
        } else {
            if (c + 1 < nc) {
                load_stage(c + 1, stage ^ 1);
                asm volatile("cp.async.wait_group 1;" ::: "memory");
            } else {
                asm volatile("cp.async.wait_group 0;" ::: "memory");
            }
            __syncthreads();
            compute_stage(stage);
            __syncthreads();
        }
    }

    // ---- epilogue ----
    const int row0 = bm + wm * 32 + (lane >> 2);
    const int col0 = bn + wn * 64 + (lane & 3) * 2;
#pragma unroll
    for (int m = 0; m < 2; m++) {
#pragma unroll
        for (int nt = 0; nt < 8; nt++) {
            const int r = row0 + m * 16;
            const int cc = col0 + nt * 8;
            float b0 = 0.f, b1 = 0.f;
            if (bias) { b0 = bias[cc]; b1 = bias[cc + 1]; }
            const float x0 = acc[m][nt][0] + b0, x1 = acc[m][nt][1] + b1;
            const float y0 = acc[m][nt][2] + b0, y1 = acc[m][nt][3] + b1;
            if (MODE == 0) {
                float* p0 = Cf + (size_t)bz * sC + (size_t)r * N + cc;
                float* p1 = Cf + (size_t)bz * sC + (size_t)(r + 8) * N + cc;
                *(float2*)p0 = make_float2(x0, x1);
                *(float2*)p1 = make_float2(y0, y1);
            } else if (MODE == 2) {
                *(uint32_t*)(Chi + (size_t)bz * sC + (size_t)r * N + cc) = packh(x1, x0);
                *(uint32_t*)(Chi + (size_t)bz * sC + (size_t)(r + 8) * N + cc) = packh(y1, y0);
            } else {
                const uint32_t hx = packh(x1, x0);
                const float2 fx = h2f(hx);
                const uint32_t lx = packh(x1 - fx.y, x0 - fx.x);
                const uint32_t hy = packh(y1, y0);
                const float2 fy = h2f(hy);
                const uint32_t ly = packh(y1 - fy.y, y0 - fy.x);
                *(uint32_t*)(Chi + (size_t)bz * sC + (size_t)r * N + cc) = hx;
                *(uint32_t*)(Clo + (size_t)bz * sC + (size_t)r * N + cc) = lx;
                *(uint32_t*)(Chi + (size_t)bz * sC + (size_t)(r + 8) * N + cc) = hy;
                *(uint32_t*)(Clo + (size_t)bz * sC + (size_t)(r + 8) * N + cc) = ly;
            }
        }
    }
}

// ---------------- fp32 -> fp16 hi/lo split (flat; small weight arrays) ------
__global__ __launch_bounds__(256) void convert_split(
    const float4* __restrict__ in, uint2* __restrict__ hi, uint2* __restrict__ lo, size_t n4)
{
    size_t i = (size_t)blockIdx.x * blockDim.x + threadIdx.x;
    if (i >= n4) return;
    const float4 v = in[i];
    const uint32_t h01 = packh(v.y, v.x);
    const uint32_t h23 = packh(v.w, v.z);
    const float2 f01 = h2f(h01), f23 = h2f(h23);
    const uint32_t l01 = packh(v.y - f01.y, v.x - f01.x);
    const uint32_t l23 = packh(v.w - f23.y, v.z - f23.x);
    hi[i] = make_uint2(h01, h23);
    lo[i] = make_uint2(l01, l23);
}

// ---------------- fp32 [R,C] -> transposed f16 hi/lo [C,R], batched --------
__global__ __launch_bounds__(256) void transpose_split(
    const float* __restrict__ in, f16* __restrict__ ohi, f16* __restrict__ olo,
    int R, int C, size_t sI, size_t sO)
{
    __shared__ float t[32][33];
    in  += (size_t)blockIdx.z * sI;
    ohi += (size_t)blockIdx.z * sO;
    olo += (size_t)blockIdx.z * sO;
    const int r0 = blockIdx.y * 32, c0 = blockIdx.x * 32;
    const int tx = threadIdx.x, ty = threadIdx.y;
#pragma unroll
    for (int j = ty; j < 32; j += 8)
        t[j][tx] = in[(size_t)(r0 + j) * C + c0 + tx];
    __syncthreads();
    // paired-row uint32 stores (2 halves per store)
    const int rr = (tx & 15) * 2;
    const int jb = ty + (tx >> 4) * 8;
#pragma unroll
    for (int it = 0; it < 2; it++) {
        const int j = jb + it * 16;
        const float v0 = t[rr][j], v1 = t[rr + 1][j];
        const uint32_t h = packh(v1, v0);
        const float2 f = h2f(h);
        const uint32_t l = packh(v1 - f.y, v0 - f.x);
        *(uint32_t*)(ohi + (size_t)(c0 + j) * R + r0 + rr) = h;
        *(uint32_t*)(olo + (size_t)(c0 + j) * R + r0 + rr) = l;
    }
}

// ---------------- w = Wk . bq ----------------
__global__ __launch_bounds__(256) void matvec_w(
    const float* __restrict__ Wk, const float* __restrict__ bq, float* __restrict__ w)
{
    const int d = blockIdx.x * 8 + (threadIdx.x >> 5);
    const int lane = threadIdx.x & 31;
    float s = 0.f;
    for (int e = lane; e < DQ; e += 32) s += Wk[(size_t)d * DQ + e] * bq[e];
#pragma unroll
    for (int o = 16; o > 0; o >>= 1) s += __shfl_xor_sync(0xFFFFFFFFu, s, o);
    if (lane == 0) w[d] = s;
}

// ---------------- vvec[r] = key[r,:] . w ----------------
__global__ __launch_bounds__(256) void matvec_v(
    const float* __restrict__ key, const float* __restrict__ w, float* __restrict__ vvec)
{
    const int r = blockIdx.x * 8 + (threadIdx.x >> 5);
    const int lane = threadIdx.x & 31;
    float s = 0.f;
    for (int d = lane; d < DK; d += 32) s += key[(size_t)r * DK + d] * w[d];
#pragma unroll
    for (int o = 16; o > 0; o >>= 1) s += __shfl_xor_sync(0xFFFFFFFFu, s, o);
    if (lane == 0) vvec[r] = s;
}

// ---------------- softmax rows (+column bias) -> f16 probs (hi only) --------
__global__ __launch_bounds__(256) void softmax_ph(
    const float* __restrict__ S, const float* __restrict__ vvec, f16* __restrict__ Phi)
{
    __shared__ float red[8];
    const size_t row = blockIdx.x;
    const float4* p4 = (const float4*)(S + row * (size_t)SLK);
    const float4* v4 = (const float4*)(vvec + (row >> 11) * (size_t)SLK);
    const int tid = threadIdx.x;

    float xv[8];
    {
        const float4 a = p4[tid], b = p4[tid + 256];
        const float4 va = v4[tid], vb = v4[tid + 256];
        xv[0] = a.x + va.x; xv[1] = a.y + va.y; xv[2] = a.z + va.z; xv[3] = a.w + va.w;
        xv[4] = b.x + vb.x; xv[5] = b.y + vb.y; xv[6] = b.z + vb.z; xv[7] = b.w + vb.w;
    }

    float m = -1e30f;
#pragma unroll
    for (int j = 0; j < 8; j++) m = fmaxf(m, xv[j]);
#pragma unroll
    for (int o = 16; o > 0; o >>= 1) m = fmaxf(m, __shfl_xor_sync(0xFFFFFFFFu, m, o));
    if ((tid & 31) == 0) red[tid >> 5] = m;
    __syncthreads();
    if (tid < 32) {
        float v = (tid < 8) ? red[tid] : -1e30f;
#pragma unroll
        for (int o = 4; o > 0; o >>= 1) v = fmaxf(v, __shfl_xor_sync(0xFFFFFFFFu, v, o));
        if (tid == 0) red[0] = v;
    }
    __syncthreads();
    m = red[0];
    __syncthreads();

    float s = 0.0f;
#pragma unroll
    for (int j = 0; j < 8; j++) { xv[j] = expf(xv[j] - m); s += xv[j]; }
#pragma unroll
    for (int o = 16; o > 0; o >>= 1) s += __shfl_xor_sync(0xFFFFFFFFu, s, o);
    if ((tid & 31) == 0) red[tid >> 5] = s;
    __syncthreads();
    if (tid < 32) {
        float v = (tid < 8) ? red[tid] : 0.0f;
#pragma unroll
        for (int o = 4; o > 0; o >>= 1) v += __shfl_xor_sync(0xFFFFFFFFu, v, o);
        if (tid == 0) red[0] = v;
    }
    __syncthreads();
    const float inv = 1.0f / red[0];

    uint2* out = (uint2*)(Phi + row * (size_t)SLK);
    out[tid]       = make_uint2(packh(xv[1] * inv, xv[0] * inv), packh(xv[3] * inv, xv[2] * inv));
    out[tid + 256] = make_uint2(packh(xv[5] * inv, xv[4] * inv), packh(xv[7] * inv, xv[6] * inv));
}

// ============================================================================
extern "C" void kernel_launch(void* const* d_in, const int* in_sizes, int n_in,
                              void* d_out, int out_size)
{
    const float* query = (const float*)d_in[0];
    const float* key   = (const float*)d_in[1];
    const float* value = (const float*)d_in[2];
    const float* Wq    = (const float*)d_in[3];
    const float* bq    = (const float*)d_in[4];
    const float* Wk    = (const float*)d_in[5];
    const float* bk    = (const float*)d_in[6];   // cancels in softmax (row-const)
    const float* Wv    = (const float*)d_in[7];
    const float* bv    = (const float*)d_in[8];
    float* out = (float*)d_out;
    (void)bk;

    f16 *wqh, *wql, *wkh, *wkl, *wvth, *wvtl;
    f16 *vth, *vtl, *mth, *mtl, *th, *uh, *ul, *ph;
    float *s, *wbq, *vvec;
    cudaGetSymbolAddress((void**)&wqh, g_wq_hi);  cudaGetSymbolAddress((void**)&wql, g_wq_lo);
    cudaGetSymbolAddress((void**)&wkh, g_wk_hi);  cudaGetSymbolAddress((void**)&wkl, g_wk_lo);
    cudaGetSymbolAddress((void**)&wvth, g_wvt_hi); cudaGetSymbolAddress((void**)&wvtl, g_wvt_lo);
    cudaGetSymbolAddress((void**)&vth, g_vt_hi);  cudaGetSymbolAddress((void**)&vtl, g_vt_lo);
    cudaGetSymbolAddress((void**)&mth, g_mt_hi);  cudaGetSymbolAddress((void**)&mtl, g_mt_lo);
    cudaGetSymbolAddress((void**)&th, g_t_hi);
    cudaGetSymbolAddress((void**)&uh, g_u_hi);    cudaGetSymbolAddress((void**)&ul, g_u_lo);
    cudaGetSymbolAddress((void**)&ph, g_p_hi);
    cudaGetSymbolAddress((void**)&s, g_s);
    cudaGetSymbolAddress((void**)&wbq, g_wbq);
    cudaGetSymbolAddress((void**)&vvec, g_vvec);

    const int SM_MT  = 2 * 4 * TILEB;            // 81920 (P3 plain)
    const int SM_T   = 2 * 4 * TILEB + 16384;    // 98304 (P3 + AF32 scratch)
    const int SM_S   = 2 * 3 * TILEB + 16384;    // 77824 (P2 + BF32 scratch)
    const int SM_U   = 2 * 3 * TILEB;            // 61440 (P2 plain)
    const int SM_OUT = 2 * 4 * TILEB;            // 81920 (P3 plain)
    cudaFuncSetAttribute((const void*)gemm_mma<3, 1, 0, 0>, cudaFuncAttributeMaxDynamicSharedMemorySize, SM_MT);
    cudaFuncSetAttribute((const void*)gemm_mma<3, 2, 1, 0>, cudaFuncAttributeMaxDynamicSharedMemorySize, SM_T);
    cudaFuncSetAttribute((const void*)gemm_mma<2, 0, 0, 1>, cudaFuncAttributeMaxDynamicSharedMemorySize, SM_S);
    cudaFuncSetAttribute((const void*)gemm_mma<2, 1, 0, 0>, cudaFuncAttributeMaxDynamicSharedMemorySize, SM_U);
    cudaFuncSetAttribute((const void*)gemm_mma<3, 0, 0, 0>, cudaFuncAttributeMaxDynamicSharedMemorySize, SM_OUT);

    const dim3 tb(32, 8, 1);

    // ---- weight splits (small) ----
    convert_split<<<(unsigned)((size_t)DQ * DQ / 4 / 256), 256>>>(
        (const float4*)Wq, (uint2*)wqh, (uint2*)wql, (size_t)DQ * DQ / 4);
    convert_split<<<(unsigned)((size_t)DK * DQ / 4 / 256), 256>>>(
        (const float4*)Wk, (uint2*)wkh, (uint2*)wkl, (size_t)DK * DQ / 4);
    transpose_split<<<dim3(DQ / 32, DV / 32, 1), tb>>>(Wv, wvth, wvtl, DV, DQ, 0, 0);
    transpose_split<<<dim3(DV / 32, SLK / 32, BB), tb>>>(
        value, vth, vtl, SLK, DV, (size_t)SLK * DV, (size_t)DV * SLK);

    // ---- bias correction vector (bq path; bk cancels) ----
    matvec_w<<<DK / 8, 256>>>(Wk, bq, wbq);
    matvec_v<<<MFLAT / 8, 256>>>(key, wbq, vvec);

    // ---- Mt = Wk Wq^T : [512,1024], 3-pass, split out ----
    gemm_mma<3, 1, 0, 0><<<dim3(DQ / 128, DK / 128, 1), 256, SM_MT>>>(
        wkh, wkl, nullptr, wqh, wql, nullptr, nullptr,
        nullptr, mth, mtl, DK, DQ, DQ, 0, 0, 0);

    // ---- T = q Mt^T : [16384,512], 3-pass, A from fp32 query, f16-hi out ----
    gemm_mma<3, 2, 1, 0><<<dim3(DK / 128, MFLAT / 128, 1), 256, SM_T>>>(
        nullptr, nullptr, query, mth, mtl, nullptr, nullptr,
        nullptr, th, nullptr, MFLAT, DK, DQ, 0, 0, 0);

    // ---- S = T key^T per batch : 2-pass, B from fp32 key, fp32 out ----
    gemm_mma<2, 0, 0, 1><<<dim3(SLK / 128, SLQ / 128, BB), 256, SM_S>>>(
        th, nullptr, nullptr, nullptr, nullptr, key, nullptr,
        s, nullptr, nullptr,
        SLQ, SLK, DK, (size_t)SLQ * DK, (size_t)SLK * DK, (size_t)SLQ * SLK);

    // ---- softmax (+vvec column bias) -> f16 probs ----
    softmax_ph<<<BB * SLQ, 256>>>(s, vvec, ph);

    // ---- U = P value per batch : 2-pass, split out ----
    gemm_mma<2, 1, 0, 0><<<dim3(DV / 128, SLQ / 128, BB), 256, SM_U>>>(
        ph, nullptr, nullptr, vth, vtl, nullptr, nullptr,
        nullptr, uh, ul,
        SLQ, DV, SLK, (size_t)SLQ * SLK, (size_t)DV * SLK, (size_t)SLQ * DV);

    // ---- out = U Wv + bv per batch : 3-pass, fp32 out ----
    gemm_mma<3, 0, 0, 0><<<dim3(DQ / 128, SLQ / 128, BB), 256, SM_OUT>>>(
        uh, ul, nullptr, wvth, wvtl, nullptr, bv,
        out, nullptr, nullptr,
        SLQ, DQ, DV, (size_t)SLQ * DV, 0, (size_t)SLQ * DQ);
}